// round 2
// baseline (speedup 1.0000x reference)
#include <cuda_runtime.h>
#include <math.h>

// Problem constants (fixed shapes from reference)
#define T_TOKENS 1024      // B*S = 2*512
#define H_DIM    2048
#define I_DIM    1408
#define SI_DIM   5632
#define NE       8

#define BM 64
#define BN 64
#define BK 16

// ---------------------------------------------------------------------------
// Scratch (no cudaMalloc allowed -> __device__ globals)
// ---------------------------------------------------------------------------
__device__ int   g_cnt[NE];
__device__ int   g_tok [NE * T_TOKENS];
__device__ int   g_slot[NE * T_TOKENS];
__device__ float g_wt  [NE * T_TOKENS];
__device__ float g_sgate[T_TOKENS];
__device__ float g_act  [(size_t)NE * T_TOKENS * I_DIM];       // silu(g)*u per expert row
__device__ float g_shact[(size_t)T_TOKENS * SI_DIM];           // shared expert intermediate
__device__ float g_contrib[(size_t)T_TOKENS * 2 * H_DIM];      // per (token, k-slot) expert output * weight

// ---------------------------------------------------------------------------
__global__ void zero_cnt_kernel() {
    if (threadIdx.x < NE) g_cnt[threadIdx.x] = 0;
}

// Router: logits, softmax, top-2 selection, per-expert token lists, shared gate
__global__ __launch_bounds__(256) void router_kernel(
    const float* __restrict__ hidden,
    const float* __restrict__ gate_w,          // [H, E]
    const float* __restrict__ shared_gate_w,   // [H]
    float* __restrict__ out_logits)            // [T, E]
{
    const int t = blockIdx.x;
    __shared__ float sh[H_DIM];
    __shared__ float slog[NE];
    __shared__ float sred[256];

    const float* hrow = hidden + (size_t)t * H_DIM;
    for (int i = threadIdx.x; i < H_DIM; i += 256) sh[i] = hrow[i];
    __syncthreads();

    const int warp = threadIdx.x >> 5;
    const int lane = threadIdx.x & 31;

    // each warp computes one expert logit
    float sum = 0.f;
    for (int k = lane; k < H_DIM; k += 32) sum += sh[k] * gate_w[k * NE + warp];
    #pragma unroll
    for (int o = 16; o; o >>= 1) sum += __shfl_down_sync(0xffffffffu, sum, o);
    if (lane == 0) slog[warp] = sum;

    // shared expert gate dot product (all threads)
    float s2 = 0.f;
    for (int k = threadIdx.x; k < H_DIM; k += 256) s2 += sh[k] * shared_gate_w[k];
    sred[threadIdx.x] = s2;
    __syncthreads();
    for (int st = 128; st; st >>= 1) {
        if (threadIdx.x < st) sred[threadIdx.x] += sred[threadIdx.x + st];
        __syncthreads();
    }

    if (threadIdx.x == 0) {
        float lg[NE];
        float mx = -1e30f;
        #pragma unroll
        for (int e = 0; e < NE; ++e) { lg[e] = slog[e]; mx = fmaxf(mx, lg[e]); }
        float p[NE]; float den = 0.f;
        #pragma unroll
        for (int e = 0; e < NE; ++e) { p[e] = expf(lg[e] - mx); den += p[e]; }
        float inv = 1.f / den;
        #pragma unroll
        for (int e = 0; e < NE; ++e) {
            p[e] *= inv;
            out_logits[(size_t)t * NE + e] = lg[e];
        }
        // top-2 (strict > keeps lowest index on ties, matching jax top_k)
        int i0 = 0;
        #pragma unroll
        for (int e = 1; e < NE; ++e) if (p[e] > p[i0]) i0 = e;
        int i1 = -1;
        #pragma unroll
        for (int e = 0; e < NE; ++e) {
            if (e == i0) continue;
            if (i1 < 0 || p[e] > p[i1]) i1 = e;
        }
        int pos0 = atomicAdd(&g_cnt[i0], 1);
        g_tok [i0 * T_TOKENS + pos0] = t;
        g_slot[i0 * T_TOKENS + pos0] = 0;
        g_wt  [i0 * T_TOKENS + pos0] = p[i0];
        int pos1 = atomicAdd(&g_cnt[i1], 1);
        g_tok [i1 * T_TOKENS + pos1] = t;
        g_slot[i1 * T_TOKENS + pos1] = 1;
        g_wt  [i1 * T_TOKENS + pos1] = p[i1];

        g_sgate[t] = 1.f / (1.f + expf(-sred[0]));
    }
}

// ---------------------------------------------------------------------------
// Expert gate+up GEMM (gathered rows), fused SiLU(g)*u epilogue.
// A: hidden[tok[m], :]  (M=cnt[e], K=H)   B: w_gate/w_up [H, I]
// ---------------------------------------------------------------------------
__global__ __launch_bounds__(256) void gateup_expert_kernel(
    const float* __restrict__ hidden,
    const float* __restrict__ w_gate,
    const float* __restrict__ w_up)
{
    const int e = blockIdx.z;
    const int cnt = g_cnt[e];
    const int m0 = blockIdx.y * BM;
    if (m0 >= cnt) return;
    const int n0 = blockIdx.x * BN;

    __shared__ float As[BK][BM + 4];
    __shared__ float Bg[BK][BN];
    __shared__ float Bu[BK][BN];

    const int tid = threadIdx.x;
    const int tx = tid & 15, ty = tid >> 4;

    const int arow = tid >> 2;
    const int akk  = (tid & 3) * 4;
    const int gm = m0 + arow;
    const int tok = (gm < cnt) ? g_tok[e * T_TOKENS + gm] : 0;
    const float* arow_ptr = hidden + (size_t)tok * H_DIM;

    const int bk = tid >> 4;
    const int bn = (tid & 15) * 4;
    const float* Bg_ptr = w_gate + (size_t)e * H_DIM * I_DIM + n0 + bn;
    const float* Bu_ptr = w_up   + (size_t)e * H_DIM * I_DIM + n0 + bn;

    float accg[4][4] = {}; float accu[4][4] = {};

    for (int k0 = 0; k0 < H_DIM; k0 += BK) {
        float4 av = *(const float4*)(arow_ptr + k0 + akk);
        As[akk + 0][arow] = av.x; As[akk + 1][arow] = av.y;
        As[akk + 2][arow] = av.z; As[akk + 3][arow] = av.w;
        *(float4*)&Bg[bk][bn] = *(const float4*)(Bg_ptr + (size_t)(k0 + bk) * I_DIM);
        *(float4*)&Bu[bk][bn] = *(const float4*)(Bu_ptr + (size_t)(k0 + bk) * I_DIM);
        __syncthreads();
        #pragma unroll
        for (int k = 0; k < BK; ++k) {
            float ra[4], rg[4], ru[4];
            #pragma unroll
            for (int i = 0; i < 4; ++i) ra[i] = As[k][ty * 4 + i];
            #pragma unroll
            for (int j = 0; j < 4; ++j) { rg[j] = Bg[k][tx * 4 + j]; ru[j] = Bu[k][tx * 4 + j]; }
            #pragma unroll
            for (int i = 0; i < 4; ++i)
                #pragma unroll
                for (int j = 0; j < 4; ++j) {
                    accg[i][j] += ra[i] * rg[j];
                    accu[i][j] += ra[i] * ru[j];
                }
        }
        __syncthreads();
    }

    #pragma unroll
    for (int i = 0; i < 4; ++i) {
        const int m = m0 + ty * 4 + i;
        if (m >= cnt) continue;
        float* orow = g_act + ((size_t)e * T_TOKENS + m) * I_DIM + n0 + tx * 4;
        #pragma unroll
        for (int j = 0; j < 4; ++j) {
            float g = accg[i][j], u = accu[i][j];
            orow[j] = (g / (1.f + expf(-g))) * u;
        }
    }
}

// ---------------------------------------------------------------------------
// Expert down GEMM: contrib[(tok,slot)] = w * act @ w_down[e]
// A: g_act (M=cnt[e], K=I)   B: w_down [I, H]
// ---------------------------------------------------------------------------
__global__ __launch_bounds__(256) void down_expert_kernel(
    const float* __restrict__ w_down)
{
    const int e = blockIdx.z;
    const int cnt = g_cnt[e];
    const int m0 = blockIdx.y * BM;
    if (m0 >= cnt) return;
    const int n0 = blockIdx.x * BN;

    __shared__ float As[BK][BM + 4];
    __shared__ float Bs[BK][BN];

    const int tid = threadIdx.x;
    const int tx = tid & 15, ty = tid >> 4;

    const int arow = tid >> 2;
    const int akk  = (tid & 3) * 4;
    const float* arow_ptr = g_act + ((size_t)e * T_TOKENS + m0 + arow) * I_DIM;

    const int bk = tid >> 4;
    const int bn = (tid & 15) * 4;
    const float* B_ptr = w_down + (size_t)e * I_DIM * H_DIM + n0 + bn;

    float acc[4][4] = {};

    for (int k0 = 0; k0 < I_DIM; k0 += BK) {
        float4 av = *(const float4*)(arow_ptr + k0 + akk);
        As[akk + 0][arow] = av.x; As[akk + 1][arow] = av.y;
        As[akk + 2][arow] = av.z; As[akk + 3][arow] = av.w;
        *(float4*)&Bs[bk][bn] = *(const float4*)(B_ptr + (size_t)(k0 + bk) * H_DIM);
        __syncthreads();
        #pragma unroll
        for (int k = 0; k < BK; ++k) {
            float ra[4], rb[4];
            #pragma unroll
            for (int i = 0; i < 4; ++i) ra[i] = As[k][ty * 4 + i];
            #pragma unroll
            for (int j = 0; j < 4; ++j) rb[j] = Bs[k][tx * 4 + j];
            #pragma unroll
            for (int i = 0; i < 4; ++i)
                #pragma unroll
                for (int j = 0; j < 4; ++j) acc[i][j] += ra[i] * rb[j];
        }
        __syncthreads();
    }

    #pragma unroll
    for (int i = 0; i < 4; ++i) {
        const int m = m0 + ty * 4 + i;
        if (m >= cnt) continue;
        const float w  = g_wt [e * T_TOKENS + m];
        const int tok  = g_tok[e * T_TOKENS + m];
        const int slot = g_slot[e * T_TOKENS + m];
        float* orow = g_contrib + ((size_t)tok * 2 + slot) * H_DIM + n0 + tx * 4;
        #pragma unroll
        for (int j = 0; j < 4; ++j) orow[j] = acc[i][j] * w;
    }
}

// ---------------------------------------------------------------------------
// Shared expert gate+up: shact = silu(h@sw_gate) * (h@sw_up)   [T, SI]
// ---------------------------------------------------------------------------
__global__ __launch_bounds__(256) void gateup_shared_kernel(
    const float* __restrict__ hidden,
    const float* __restrict__ sw_gate,
    const float* __restrict__ sw_up)
{
    const int m0 = blockIdx.y * BM;
    const int n0 = blockIdx.x * BN;

    __shared__ float As[BK][BM + 4];
    __shared__ float Bg[BK][BN];
    __shared__ float Bu[BK][BN];

    const int tid = threadIdx.x;
    const int tx = tid & 15, ty = tid >> 4;

    const int arow = tid >> 2;
    const int akk  = (tid & 3) * 4;
    const float* arow_ptr = hidden + (size_t)(m0 + arow) * H_DIM;

    const int bk = tid >> 4;
    const int bn = (tid & 15) * 4;
    const float* Bg_ptr = sw_gate + n0 + bn;
    const float* Bu_ptr = sw_up   + n0 + bn;

    float accg[4][4] = {}; float accu[4][4] = {};

    for (int k0 = 0; k0 < H_DIM; k0 += BK) {
        float4 av = *(const float4*)(arow_ptr + k0 + akk);
        As[akk + 0][arow] = av.x; As[akk + 1][arow] = av.y;
        As[akk + 2][arow] = av.z; As[akk + 3][arow] = av.w;
        *(float4*)&Bg[bk][bn] = *(const float4*)(Bg_ptr + (size_t)(k0 + bk) * SI_DIM);
        *(float4*)&Bu[bk][bn] = *(const float4*)(Bu_ptr + (size_t)(k0 + bk) * SI_DIM);
        __syncthreads();
        #pragma unroll
        for (int k = 0; k < BK; ++k) {
            float ra[4], rg[4], ru[4];
            #pragma unroll
            for (int i = 0; i < 4; ++i) ra[i] = As[k][ty * 4 + i];
            #pragma unroll
            for (int j = 0; j < 4; ++j) { rg[j] = Bg[k][tx * 4 + j]; ru[j] = Bu[k][tx * 4 + j]; }
            #pragma unroll
            for (int i = 0; i < 4; ++i)
                #pragma unroll
                for (int j = 0; j < 4; ++j) {
                    accg[i][j] += ra[i] * rg[j];
                    accu[i][j] += ra[i] * ru[j];
                }
        }
        __syncthreads();
    }

    #pragma unroll
    for (int i = 0; i < 4; ++i) {
        const int m = m0 + ty * 4 + i;
        float* orow = g_shact + (size_t)m * SI_DIM + n0 + tx * 4;
        #pragma unroll
        for (int j = 0; j < 4; ++j) {
            float g = accg[i][j], u = accu[i][j];
            orow[j] = (g / (1.f + expf(-g))) * u;
        }
    }
}

// ---------------------------------------------------------------------------
// Shared down GEMM + final combine:
// out[t] = sigmoid_gate[t] * (shact @ sw_down)[t] + contrib[t,0] + contrib[t,1]
// ---------------------------------------------------------------------------
__global__ __launch_bounds__(256) void down_shared_kernel(
    const float* __restrict__ sw_down,
    float* __restrict__ out)
{
    const int m0 = blockIdx.y * BM;
    const int n0 = blockIdx.x * BN;

    __shared__ float As[BK][BM + 4];
    __shared__ float Bs[BK][BN];

    const int tid = threadIdx.x;
    const int tx = tid & 15, ty = tid >> 4;

    const int arow = tid >> 2;
    const int akk  = (tid & 3) * 4;
    const float* arow_ptr = g_shact + (size_t)(m0 + arow) * SI_DIM;

    const int bk = tid >> 4;
    const int bn = (tid & 15) * 4;
    const float* B_ptr = sw_down + n0 + bn;

    float acc[4][4] = {};

    for (int k0 = 0; k0 < SI_DIM; k0 += BK) {
        float4 av = *(const float4*)(arow_ptr + k0 + akk);
        As[akk + 0][arow] = av.x; As[akk + 1][arow] = av.y;
        As[akk + 2][arow] = av.z; As[akk + 3][arow] = av.w;
        *(float4*)&Bs[bk][bn] = *(const float4*)(B_ptr + (size_t)(k0 + bk) * H_DIM);
        __syncthreads();
        #pragma unroll
        for (int k = 0; k < BK; ++k) {
            float ra[4], rb[4];
            #pragma unroll
            for (int i = 0; i < 4; ++i) ra[i] = As[k][ty * 4 + i];
            #pragma unroll
            for (int j = 0; j < 4; ++j) rb[j] = Bs[k][tx * 4 + j];
            #pragma unroll
            for (int i = 0; i < 4; ++i)
                #pragma unroll
                for (int j = 0; j < 4; ++j) acc[i][j] += ra[i] * rb[j];
        }
        __syncthreads();
    }

    #pragma unroll
    for (int i = 0; i < 4; ++i) {
        const int m = m0 + ty * 4 + i;
        const float sg = g_sgate[m];
        float* orow = out + (size_t)m * H_DIM + n0 + tx * 4;
        const float* c0 = g_contrib + ((size_t)m * 2 + 0) * H_DIM + n0 + tx * 4;
        const float* c1 = g_contrib + ((size_t)m * 2 + 1) * H_DIM + n0 + tx * 4;
        #pragma unroll
        for (int j = 0; j < 4; ++j) orow[j] = sg * acc[i][j] + c0[j] + c1[j];
    }
}

// ---------------------------------------------------------------------------
extern "C" void kernel_launch(void* const* d_in, const int* in_sizes, int n_in,
                              void* d_out, int out_size)
{
    const float* hidden        = (const float*)d_in[0];
    const float* gate_w        = (const float*)d_in[1];
    const float* w_gate        = (const float*)d_in[2];
    const float* w_up          = (const float*)d_in[3];
    const float* w_down        = (const float*)d_in[4];
    const float* sw_gate       = (const float*)d_in[5];
    const float* sw_up         = (const float*)d_in[6];
    const float* sw_down       = (const float*)d_in[7];
    const float* shared_gate_w = (const float*)d_in[8];

    float* out        = (float*)d_out;
    float* out_logits = out + (size_t)T_TOKENS * H_DIM;

    zero_cnt_kernel<<<1, 32>>>();
    router_kernel<<<T_TOKENS, 256>>>(hidden, gate_w, shared_gate_w, out_logits);
    gateup_expert_kernel<<<dim3(I_DIM / BN, T_TOKENS / BM, NE), 256>>>(hidden, w_gate, w_up);
    down_expert_kernel  <<<dim3(H_DIM / BN, T_TOKENS / BM, NE), 256>>>(w_down);
    gateup_shared_kernel<<<dim3(SI_DIM / BN, T_TOKENS / BM), 256>>>(hidden, sw_gate, sw_up);
    down_shared_kernel  <<<dim3(H_DIM / BN, T_TOKENS / BM), 256>>>(sw_down, out);
}

// round 3
// speedup vs baseline: 1.0246x; 1.0246x over previous
#include <cuda_runtime.h>
#include <math.h>

// Problem constants (fixed shapes from reference)
#define T_TOKENS 1024      // B*S = 2*512
#define H_DIM    2048
#define I_DIM    1408
#define SI_DIM   5632
#define NE       8

// Big-tile GEMM config
#define BK 16

// ---------------------------------------------------------------------------
// Scratch (no cudaMalloc allowed -> __device__ globals)
// ---------------------------------------------------------------------------
__device__ int   g_cnt[NE];
__device__ int   g_tok [NE * T_TOKENS];
__device__ int   g_slot[NE * T_TOKENS];
__device__ float g_wt  [NE * T_TOKENS];
__device__ float g_sgate[T_TOKENS];
__device__ float g_act  [(size_t)NE * T_TOKENS * I_DIM];       // silu(g)*u per expert row
__device__ float g_shact[(size_t)T_TOKENS * SI_DIM];           // shared expert intermediate
__device__ float g_contrib[(size_t)T_TOKENS * 2 * H_DIM];      // per (token, k-slot) expert output * weight

// ---------------------------------------------------------------------------
__global__ void zero_cnt_kernel() {
    if (threadIdx.x < NE) g_cnt[threadIdx.x] = 0;
}

// Router: logits, softmax, top-2 selection, per-expert token lists, shared gate
__global__ __launch_bounds__(256) void router_kernel(
    const float* __restrict__ hidden,
    const float* __restrict__ gate_w,          // [H, E]
    const float* __restrict__ shared_gate_w,   // [H]
    float* __restrict__ out_logits)            // [T, E]
{
    const int t = blockIdx.x;
    __shared__ float sh[H_DIM];
    __shared__ float slog[NE];
    __shared__ float sred[256];

    const float* hrow = hidden + (size_t)t * H_DIM;
    for (int i = threadIdx.x; i < H_DIM; i += 256) sh[i] = hrow[i];
    __syncthreads();

    const int warp = threadIdx.x >> 5;
    const int lane = threadIdx.x & 31;

    // each warp computes one expert logit
    float sum = 0.f;
    for (int k = lane; k < H_DIM; k += 32) sum += sh[k] * gate_w[k * NE + warp];
    #pragma unroll
    for (int o = 16; o; o >>= 1) sum += __shfl_down_sync(0xffffffffu, sum, o);
    if (lane == 0) slog[warp] = sum;

    // shared expert gate dot product (all threads)
    float s2 = 0.f;
    for (int k = threadIdx.x; k < H_DIM; k += 256) s2 += sh[k] * shared_gate_w[k];
    sred[threadIdx.x] = s2;
    __syncthreads();
    for (int st = 128; st; st >>= 1) {
        if (threadIdx.x < st) sred[threadIdx.x] += sred[threadIdx.x + st];
        __syncthreads();
    }

    if (threadIdx.x == 0) {
        float lg[NE];
        float mx = -1e30f;
        #pragma unroll
        for (int e = 0; e < NE; ++e) { lg[e] = slog[e]; mx = fmaxf(mx, lg[e]); }
        float p[NE]; float den = 0.f;
        #pragma unroll
        for (int e = 0; e < NE; ++e) { p[e] = expf(lg[e] - mx); den += p[e]; }
        float inv = 1.f / den;
        #pragma unroll
        for (int e = 0; e < NE; ++e) {
            p[e] *= inv;
            out_logits[(size_t)t * NE + e] = lg[e];
        }
        // top-2 (strict > keeps lowest index on ties, matching jax top_k)
        int i0 = 0;
        #pragma unroll
        for (int e = 1; e < NE; ++e) if (p[e] > p[i0]) i0 = e;
        int i1 = -1;
        #pragma unroll
        for (int e = 0; e < NE; ++e) {
            if (e == i0) continue;
            if (i1 < 0 || p[e] > p[i1]) i1 = e;
        }
        int pos0 = atomicAdd(&g_cnt[i0], 1);
        g_tok [i0 * T_TOKENS + pos0] = t;
        g_slot[i0 * T_TOKENS + pos0] = 0;
        g_wt  [i0 * T_TOKENS + pos0] = p[i0];
        int pos1 = atomicAdd(&g_cnt[i1], 1);
        g_tok [i1 * T_TOKENS + pos1] = t;
        g_slot[i1 * T_TOKENS + pos1] = 1;
        g_wt  [i1 * T_TOKENS + pos1] = p[i1];

        g_sgate[t] = 1.f / (1.f + expf(-sred[0]));
    }
}

// ===========================================================================
// Dual-B gate+up GEMM core: 128(M) x 64(N) tile, 256 threads, 8x4 per-thread
// per output matrix, float4 shared loads. Fused SiLU(g)*u epilogue.
// ===========================================================================

// ---------------------------------------------------------------------------
// Expert gate+up GEMM (gathered rows).
// A: hidden[tok[m], :]  (M=cnt[e], K=H)   B: w_gate/w_up [H, I]
// ---------------------------------------------------------------------------
__global__ __launch_bounds__(256) void gateup_expert_kernel(
    const float* __restrict__ hidden,
    const float* __restrict__ w_gate,
    const float* __restrict__ w_up)
{
    const int e = blockIdx.z;
    const int cnt = g_cnt[e];
    const int m0 = blockIdx.y * 128;
    if (m0 >= cnt) return;
    const int n0 = blockIdx.x * 64;

    __shared__ float As[BK][128 + 4];
    __shared__ float Bg[BK][64];
    __shared__ float Bu[BK][64];

    const int tid = threadIdx.x;
    const int tx = tid & 15;          // n:  tx*4
    const int ty = tid >> 4;          // m:  ty*8

    // A loading: each thread loads 8 consecutive k for one m row
    const int arow = tid >> 1;            // 0..127
    const int acol = (tid & 1) * 8;       // 0 or 8
    const int gm = m0 + arow;
    const int tok = (gm < cnt) ? g_tok[e * T_TOKENS + gm] : 0;
    const float* aptr = hidden + (size_t)tok * H_DIM;

    // B loading: one float4 per thread per matrix
    const int brow = tid >> 4;             // 0..15
    const int bcol = (tid & 15) * 4;       // 0..60
    const float* gptr = w_gate + (size_t)e * H_DIM * I_DIM + n0 + bcol;
    const float* uptr = w_up   + (size_t)e * H_DIM * I_DIM + n0 + bcol;

    float accg[8][4] = {}; float accu[8][4] = {};

    for (int k0 = 0; k0 < H_DIM; k0 += BK) {
        float4 a0 = *(const float4*)(aptr + k0 + acol);
        float4 a1 = *(const float4*)(aptr + k0 + acol + 4);
        As[acol + 0][arow] = a0.x; As[acol + 1][arow] = a0.y;
        As[acol + 2][arow] = a0.z; As[acol + 3][arow] = a0.w;
        As[acol + 4][arow] = a1.x; As[acol + 5][arow] = a1.y;
        As[acol + 6][arow] = a1.z; As[acol + 7][arow] = a1.w;
        *(float4*)&Bg[brow][bcol] = *(const float4*)(gptr + (size_t)(k0 + brow) * I_DIM);
        *(float4*)&Bu[brow][bcol] = *(const float4*)(uptr + (size_t)(k0 + brow) * I_DIM);
        __syncthreads();
        #pragma unroll
        for (int k = 0; k < BK; ++k) {
            float ra[8], rg[4], ru[4];
            float4 ra0 = *(const float4*)&As[k][ty * 8];
            float4 ra1 = *(const float4*)&As[k][ty * 8 + 4];
            ra[0]=ra0.x; ra[1]=ra0.y; ra[2]=ra0.z; ra[3]=ra0.w;
            ra[4]=ra1.x; ra[5]=ra1.y; ra[6]=ra1.z; ra[7]=ra1.w;
            float4 rgv = *(const float4*)&Bg[k][tx * 4];
            float4 ruv = *(const float4*)&Bu[k][tx * 4];
            rg[0]=rgv.x; rg[1]=rgv.y; rg[2]=rgv.z; rg[3]=rgv.w;
            ru[0]=ruv.x; ru[1]=ruv.y; ru[2]=ruv.z; ru[3]=ruv.w;
            #pragma unroll
            for (int i = 0; i < 8; ++i)
                #pragma unroll
                for (int j = 0; j < 4; ++j) {
                    accg[i][j] += ra[i] * rg[j];
                    accu[i][j] += ra[i] * ru[j];
                }
        }
        __syncthreads();
    }

    #pragma unroll
    for (int i = 0; i < 8; ++i) {
        const int m = m0 + ty * 8 + i;
        if (m >= cnt) continue;
        float4 o;
        float* orow = g_act + ((size_t)e * T_TOKENS + m) * I_DIM + n0 + tx * 4;
        float g0 = accg[i][0], g1 = accg[i][1], g2 = accg[i][2], g3 = accg[i][3];
        o.x = (g0 / (1.f + expf(-g0))) * accu[i][0];
        o.y = (g1 / (1.f + expf(-g1))) * accu[i][1];
        o.z = (g2 / (1.f + expf(-g2))) * accu[i][2];
        o.w = (g3 / (1.f + expf(-g3))) * accu[i][3];
        *(float4*)orow = o;
    }
}

// ---------------------------------------------------------------------------
// Expert down GEMM: contrib[(tok,slot)] = w * act @ w_down[e]
// 128x128 tile, 8x8 per thread.
// ---------------------------------------------------------------------------
__global__ __launch_bounds__(256) void down_expert_kernel(
    const float* __restrict__ w_down)
{
    const int e = blockIdx.z;
    const int cnt = g_cnt[e];
    const int m0 = blockIdx.y * 128;
    if (m0 >= cnt) return;
    const int n0 = blockIdx.x * 128;

    __shared__ float As[BK][128 + 4];
    __shared__ float Bs[BK][128];

    const int tid = threadIdx.x;
    const int tx = tid & 15;          // n: tx*8
    const int ty = tid >> 4;          // m: ty*8

    const int arow = tid >> 1;
    const int acol = (tid & 1) * 8;
    // m0+arow < T_TOKENS always; rows >= cnt are garbage but masked at store
    const float* aptr = g_act + ((size_t)e * T_TOKENS + m0 + arow) * I_DIM;

    const int brow = tid >> 4;             // 0..15
    const int bcol = (tid & 15) * 8;       // 0..120
    const float* bptr = w_down + (size_t)e * I_DIM * H_DIM + n0 + bcol;

    float acc[8][8] = {};

    for (int k0 = 0; k0 < I_DIM; k0 += BK) {
        float4 a0 = *(const float4*)(aptr + k0 + acol);
        float4 a1 = *(const float4*)(aptr + k0 + acol + 4);
        As[acol + 0][arow] = a0.x; As[acol + 1][arow] = a0.y;
        As[acol + 2][arow] = a0.z; As[acol + 3][arow] = a0.w;
        As[acol + 4][arow] = a1.x; As[acol + 5][arow] = a1.y;
        As[acol + 6][arow] = a1.z; As[acol + 7][arow] = a1.w;
        *(float4*)&Bs[brow][bcol]     = *(const float4*)(bptr + (size_t)(k0 + brow) * H_DIM);
        *(float4*)&Bs[brow][bcol + 4] = *(const float4*)(bptr + (size_t)(k0 + brow) * H_DIM + 4);
        __syncthreads();
        #pragma unroll
        for (int k = 0; k < BK; ++k) {
            float ra[8], rb[8];
            float4 v;
            v = *(const float4*)&As[k][ty * 8];     ra[0]=v.x; ra[1]=v.y; ra[2]=v.z; ra[3]=v.w;
            v = *(const float4*)&As[k][ty * 8 + 4]; ra[4]=v.x; ra[5]=v.y; ra[6]=v.z; ra[7]=v.w;
            v = *(const float4*)&Bs[k][tx * 8];     rb[0]=v.x; rb[1]=v.y; rb[2]=v.z; rb[3]=v.w;
            v = *(const float4*)&Bs[k][tx * 8 + 4]; rb[4]=v.x; rb[5]=v.y; rb[6]=v.z; rb[7]=v.w;
            #pragma unroll
            for (int i = 0; i < 8; ++i)
                #pragma unroll
                for (int j = 0; j < 8; ++j) acc[i][j] += ra[i] * rb[j];
        }
        __syncthreads();
    }

    #pragma unroll
    for (int i = 0; i < 8; ++i) {
        const int m = m0 + ty * 8 + i;
        if (m >= cnt) continue;
        const float w  = g_wt [e * T_TOKENS + m];
        const int tok  = g_tok[e * T_TOKENS + m];
        const int slot = g_slot[e * T_TOKENS + m];
        float* orow = g_contrib + ((size_t)tok * 2 + slot) * H_DIM + n0 + tx * 8;
        float4 o0, o1;
        o0.x = acc[i][0]*w; o0.y = acc[i][1]*w; o0.z = acc[i][2]*w; o0.w = acc[i][3]*w;
        o1.x = acc[i][4]*w; o1.y = acc[i][5]*w; o1.z = acc[i][6]*w; o1.w = acc[i][7]*w;
        *(float4*)orow = o0;
        *(float4*)(orow + 4) = o1;
    }
}

// ---------------------------------------------------------------------------
// Shared expert gate+up: shact = silu(h@sw_gate) * (h@sw_up)   [T, SI]
// 128x64 dual-B tile.
// ---------------------------------------------------------------------------
__global__ __launch_bounds__(256) void gateup_shared_kernel(
    const float* __restrict__ hidden,
    const float* __restrict__ sw_gate,
    const float* __restrict__ sw_up)
{
    const int m0 = blockIdx.y * 128;
    const int n0 = blockIdx.x * 64;

    __shared__ float As[BK][128 + 4];
    __shared__ float Bg[BK][64];
    __shared__ float Bu[BK][64];

    const int tid = threadIdx.x;
    const int tx = tid & 15;
    const int ty = tid >> 4;

    const int arow = tid >> 1;
    const int acol = (tid & 1) * 8;
    const float* aptr = hidden + (size_t)(m0 + arow) * H_DIM;

    const int brow = tid >> 4;
    const int bcol = (tid & 15) * 4;
    const float* gptr = sw_gate + n0 + bcol;
    const float* uptr = sw_up   + n0 + bcol;

    float accg[8][4] = {}; float accu[8][4] = {};

    for (int k0 = 0; k0 < H_DIM; k0 += BK) {
        float4 a0 = *(const float4*)(aptr + k0 + acol);
        float4 a1 = *(const float4*)(aptr + k0 + acol + 4);
        As[acol + 0][arow] = a0.x; As[acol + 1][arow] = a0.y;
        As[acol + 2][arow] = a0.z; As[acol + 3][arow] = a0.w;
        As[acol + 4][arow] = a1.x; As[acol + 5][arow] = a1.y;
        As[acol + 6][arow] = a1.z; As[acol + 7][arow] = a1.w;
        *(float4*)&Bg[brow][bcol] = *(const float4*)(gptr + (size_t)(k0 + brow) * SI_DIM);
        *(float4*)&Bu[brow][bcol] = *(const float4*)(uptr + (size_t)(k0 + brow) * SI_DIM);
        __syncthreads();
        #pragma unroll
        for (int k = 0; k < BK; ++k) {
            float ra[8], rg[4], ru[4];
            float4 ra0 = *(const float4*)&As[k][ty * 8];
            float4 ra1 = *(const float4*)&As[k][ty * 8 + 4];
            ra[0]=ra0.x; ra[1]=ra0.y; ra[2]=ra0.z; ra[3]=ra0.w;
            ra[4]=ra1.x; ra[5]=ra1.y; ra[6]=ra1.z; ra[7]=ra1.w;
            float4 rgv = *(const float4*)&Bg[k][tx * 4];
            float4 ruv = *(const float4*)&Bu[k][tx * 4];
            rg[0]=rgv.x; rg[1]=rgv.y; rg[2]=rgv.z; rg[3]=rgv.w;
            ru[0]=ruv.x; ru[1]=ruv.y; ru[2]=ruv.z; ru[3]=ruv.w;
            #pragma unroll
            for (int i = 0; i < 8; ++i)
                #pragma unroll
                for (int j = 0; j < 4; ++j) {
                    accg[i][j] += ra[i] * rg[j];
                    accu[i][j] += ra[i] * ru[j];
                }
        }
        __syncthreads();
    }

    #pragma unroll
    for (int i = 0; i < 8; ++i) {
        const int m = m0 + ty * 8 + i;
        float* orow = g_shact + (size_t)m * SI_DIM + n0 + tx * 4;
        float4 o;
        float g0 = accg[i][0], g1 = accg[i][1], g2 = accg[i][2], g3 = accg[i][3];
        o.x = (g0 / (1.f + expf(-g0))) * accu[i][0];
        o.y = (g1 / (1.f + expf(-g1))) * accu[i][1];
        o.z = (g2 / (1.f + expf(-g2))) * accu[i][2];
        o.w = (g3 / (1.f + expf(-g3))) * accu[i][3];
        *(float4*)orow = o;
    }
}

// ---------------------------------------------------------------------------
// Shared down GEMM + final combine:
// out[t] = sigmoid_gate[t] * (shact @ sw_down)[t] + contrib[t,0] + contrib[t,1]
// 128x128 tile, 8x8 per thread.
// ---------------------------------------------------------------------------
__global__ __launch_bounds__(256) void down_shared_kernel(
    const float* __restrict__ sw_down,
    float* __restrict__ out)
{
    const int m0 = blockIdx.y * 128;
    const int n0 = blockIdx.x * 128;

    __shared__ float As[BK][128 + 4];
    __shared__ float Bs[BK][128];

    const int tid = threadIdx.x;
    const int tx = tid & 15;
    const int ty = tid >> 4;

    const int arow = tid >> 1;
    const int acol = (tid & 1) * 8;
    const float* aptr = g_shact + (size_t)(m0 + arow) * SI_DIM;

    const int brow = tid >> 4;
    const int bcol = (tid & 15) * 8;
    const float* bptr = sw_down + n0 + bcol;

    float acc[8][8] = {};

    for (int k0 = 0; k0 < SI_DIM; k0 += BK) {
        float4 a0 = *(const float4*)(aptr + k0 + acol);
        float4 a1 = *(const float4*)(aptr + k0 + acol + 4);
        As[acol + 0][arow] = a0.x; As[acol + 1][arow] = a0.y;
        As[acol + 2][arow] = a0.z; As[acol + 3][arow] = a0.w;
        As[acol + 4][arow] = a1.x; As[acol + 5][arow] = a1.y;
        As[acol + 6][arow] = a1.z; As[acol + 7][arow] = a1.w;
        *(float4*)&Bs[brow][bcol]     = *(const float4*)(bptr + (size_t)(k0 + brow) * H_DIM);
        *(float4*)&Bs[brow][bcol + 4] = *(const float4*)(bptr + (size_t)(k0 + brow) * H_DIM + 4);
        __syncthreads();
        #pragma unroll
        for (int k = 0; k < BK; ++k) {
            float ra[8], rb[8];
            float4 v;
            v = *(const float4*)&As[k][ty * 8];     ra[0]=v.x; ra[1]=v.y; ra[2]=v.z; ra[3]=v.w;
            v = *(const float4*)&As[k][ty * 8 + 4]; ra[4]=v.x; ra[5]=v.y; ra[6]=v.z; ra[7]=v.w;
            v = *(const float4*)&Bs[k][tx * 8];     rb[0]=v.x; rb[1]=v.y; rb[2]=v.z; rb[3]=v.w;
            v = *(const float4*)&Bs[k][tx * 8 + 4]; rb[4]=v.x; rb[5]=v.y; rb[6]=v.z; rb[7]=v.w;
            #pragma unroll
            for (int i = 0; i < 8; ++i)
                #pragma unroll
                for (int j = 0; j < 8; ++j) acc[i][j] += ra[i] * rb[j];
        }
        __syncthreads();
    }

    #pragma unroll
    for (int i = 0; i < 8; ++i) {
        const int m = m0 + ty * 8 + i;
        const float sg = g_sgate[m];
        float* orow = out + (size_t)m * H_DIM + n0 + tx * 8;
        const float* c0 = g_contrib + ((size_t)m * 2 + 0) * H_DIM + n0 + tx * 8;
        const float* c1 = g_contrib + ((size_t)m * 2 + 1) * H_DIM + n0 + tx * 8;
        float4 c0a = *(const float4*)c0, c0b = *(const float4*)(c0 + 4);
        float4 c1a = *(const float4*)c1, c1b = *(const float4*)(c1 + 4);
        float4 o0, o1;
        o0.x = sg * acc[i][0] + c0a.x + c1a.x;
        o0.y = sg * acc[i][1] + c0a.y + c1a.y;
        o0.z = sg * acc[i][2] + c0a.z + c1a.z;
        o0.w = sg * acc[i][3] + c0a.w + c1a.w;
        o1.x = sg * acc[i][4] + c0b.x + c1b.x;
        o1.y = sg * acc[i][5] + c0b.y + c1b.y;
        o1.z = sg * acc[i][6] + c0b.z + c1b.z;
        o1.w = sg * acc[i][7] + c0b.w + c1b.w;
        *(float4*)orow = o0;
        *(float4*)(orow + 4) = o1;
    }
}

// ---------------------------------------------------------------------------
extern "C" void kernel_launch(void* const* d_in, const int* in_sizes, int n_in,
                              void* d_out, int out_size)
{
    const float* hidden        = (const float*)d_in[0];
    const float* gate_w        = (const float*)d_in[1];
    const float* w_gate        = (const float*)d_in[2];
    const float* w_up          = (const float*)d_in[3];
    const float* w_down        = (const float*)d_in[4];
    const float* sw_gate       = (const float*)d_in[5];
    const float* sw_up         = (const float*)d_in[6];
    const float* sw_down       = (const float*)d_in[7];
    const float* shared_gate_w = (const float*)d_in[8];

    float* out        = (float*)d_out;
    float* out_logits = out + (size_t)T_TOKENS * H_DIM;

    zero_cnt_kernel<<<1, 32>>>();
    router_kernel<<<T_TOKENS, 256>>>(hidden, gate_w, shared_gate_w, out_logits);
    gateup_expert_kernel<<<dim3(I_DIM / 64, T_TOKENS / 128, NE), 256>>>(hidden, w_gate, w_up);
    down_expert_kernel  <<<dim3(H_DIM / 128, T_TOKENS / 128, NE), 256>>>(w_down);
    gateup_shared_kernel<<<dim3(SI_DIM / 64, T_TOKENS / 128), 256>>>(hidden, sw_gate, sw_up);
    down_shared_kernel  <<<dim3(H_DIM / 128, T_TOKENS / 128), 256>>>(sw_down, out);
}

// round 4
// speedup vs baseline: 1.8510x; 1.8066x over previous
#include <cuda_runtime.h>
#include <cuda_bf16.h>
#include <math.h>
#include <stdint.h>

// Problem constants
#define T_TOKENS 1024
#define H_DIM    2048
#define I_DIM    1408
#define SI_DIM   5632
#define NE       8

typedef __nv_bfloat16 bf16;
typedef __nv_bfloat162 bf162;

// ---------------------------------------------------------------------------
// Scratch (__device__ globals; no cudaMalloc allowed)
// ---------------------------------------------------------------------------
__device__ int   g_cnt[NE];
__device__ int   g_tok [NE * T_TOKENS];
__device__ int   g_slot[NE * T_TOKENS];
__device__ float g_wt  [NE * T_TOKENS];
__device__ float g_sgate[T_TOKENS];

// bf16 hi/lo splits
__device__ bf16 g_hid_hi[(size_t)T_TOKENS * H_DIM];
__device__ bf16 g_hid_lo[(size_t)T_TOKENS * H_DIM];
__device__ bf16 g_wg_hi[(size_t)NE * H_DIM * I_DIM];
__device__ bf16 g_wg_lo[(size_t)NE * H_DIM * I_DIM];
__device__ bf16 g_wu_hi[(size_t)NE * H_DIM * I_DIM];
__device__ bf16 g_wu_lo[(size_t)NE * H_DIM * I_DIM];
__device__ bf16 g_wd_hi[(size_t)NE * I_DIM * H_DIM];
__device__ bf16 g_wd_lo[(size_t)NE * I_DIM * H_DIM];
__device__ bf16 g_swg_hi[(size_t)H_DIM * SI_DIM];
__device__ bf16 g_swg_lo[(size_t)H_DIM * SI_DIM];
__device__ bf16 g_swu_hi[(size_t)H_DIM * SI_DIM];
__device__ bf16 g_swu_lo[(size_t)H_DIM * SI_DIM];
__device__ bf16 g_swd_hi[(size_t)SI_DIM * H_DIM];
__device__ bf16 g_swd_lo[(size_t)SI_DIM * H_DIM];

// intermediates
__device__ float g_tmpg[(size_t)NE * T_TOKENS * I_DIM];   // gate pre-act (also reused for shared, T*SI fits)
__device__ float g_tmpu[(size_t)NE * T_TOKENS * I_DIM];   // up  pre-act
__device__ bf16  g_act_hi[(size_t)NE * T_TOKENS * I_DIM];
__device__ bf16  g_act_lo[(size_t)NE * T_TOKENS * I_DIM];
__device__ bf16  g_shact_hi[(size_t)T_TOKENS * SI_DIM];
__device__ bf16  g_shact_lo[(size_t)T_TOKENS * SI_DIM];
__device__ float g_contrib[(size_t)T_TOKENS * 2 * H_DIM];

// ---------------------------------------------------------------------------
__global__ void zero_cnt_kernel() {
    if (threadIdx.x < NE) g_cnt[threadIdx.x] = 0;
}

// Router (fp32, unchanged math)
__global__ __launch_bounds__(256) void router_kernel(
    const float* __restrict__ hidden,
    const float* __restrict__ gate_w,
    const float* __restrict__ shared_gate_w,
    float* __restrict__ out_logits)
{
    const int t = blockIdx.x;
    __shared__ float sh[H_DIM];
    __shared__ float slog[NE];
    __shared__ float sred[256];

    const float* hrow = hidden + (size_t)t * H_DIM;
    for (int i = threadIdx.x; i < H_DIM; i += 256) sh[i] = hrow[i];
    __syncthreads();

    const int warp = threadIdx.x >> 5;
    const int lane = threadIdx.x & 31;

    float sum = 0.f;
    for (int k = lane; k < H_DIM; k += 32) sum += sh[k] * gate_w[k * NE + warp];
    #pragma unroll
    for (int o = 16; o; o >>= 1) sum += __shfl_down_sync(0xffffffffu, sum, o);
    if (lane == 0) slog[warp] = sum;

    float s2 = 0.f;
    for (int k = threadIdx.x; k < H_DIM; k += 256) s2 += sh[k] * shared_gate_w[k];
    sred[threadIdx.x] = s2;
    __syncthreads();
    for (int st = 128; st; st >>= 1) {
        if (threadIdx.x < st) sred[threadIdx.x] += sred[threadIdx.x + st];
        __syncthreads();
    }

    if (threadIdx.x == 0) {
        float lg[NE];
        float mx = -1e30f;
        #pragma unroll
        for (int e = 0; e < NE; ++e) { lg[e] = slog[e]; mx = fmaxf(mx, lg[e]); }
        float p[NE]; float den = 0.f;
        #pragma unroll
        for (int e = 0; e < NE; ++e) { p[e] = expf(lg[e] - mx); den += p[e]; }
        float inv = 1.f / den;
        #pragma unroll
        for (int e = 0; e < NE; ++e) {
            p[e] *= inv;
            out_logits[(size_t)t * NE + e] = lg[e];
        }
        int i0 = 0;
        #pragma unroll
        for (int e = 1; e < NE; ++e) if (p[e] > p[i0]) i0 = e;
        int i1 = -1;
        #pragma unroll
        for (int e = 0; e < NE; ++e) {
            if (e == i0) continue;
            if (i1 < 0 || p[e] > p[i1]) i1 = e;
        }
        int pos0 = atomicAdd(&g_cnt[i0], 1);
        g_tok [i0 * T_TOKENS + pos0] = t;
        g_slot[i0 * T_TOKENS + pos0] = 0;
        g_wt  [i0 * T_TOKENS + pos0] = p[i0];
        int pos1 = atomicAdd(&g_cnt[i1], 1);
        g_tok [i1 * T_TOKENS + pos1] = t;
        g_slot[i1 * T_TOKENS + pos1] = 1;
        g_wt  [i1 * T_TOKENS + pos1] = p[i1];

        g_sgate[t] = 1.f / (1.f + expf(-sred[0]));
    }
}

// ---------------------------------------------------------------------------
// fp32 -> bf16 hi/lo split
// ---------------------------------------------------------------------------
__global__ __launch_bounds__(256) void split_kernel(
    const float* __restrict__ src, bf16* __restrict__ hi, bf16* __restrict__ lo, int n4)
{
    for (int i = blockIdx.x * 256 + threadIdx.x; i < n4; i += gridDim.x * 256) {
        float4 v = ((const float4*)src)[i];
        bf16 hx = __float2bfloat16_rn(v.x);
        bf16 hy = __float2bfloat16_rn(v.y);
        bf16 hz = __float2bfloat16_rn(v.z);
        bf16 hw = __float2bfloat16_rn(v.w);
        bf16 lx = __float2bfloat16_rn(v.x - __bfloat162float(hx));
        bf16 ly = __float2bfloat16_rn(v.y - __bfloat162float(hy));
        bf16 lz = __float2bfloat16_rn(v.z - __bfloat162float(hz));
        bf16 lw = __float2bfloat16_rn(v.w - __bfloat162float(hw));
        ((bf162*)hi)[2 * i]     = bf162(hx, hy);
        ((bf162*)hi)[2 * i + 1] = bf162(hz, hw);
        ((bf162*)lo)[2 * i]     = bf162(lx, ly);
        ((bf162*)lo)[2 * i + 1] = bf162(lz, lw);
    }
}

// silu(g)*u -> bf16 hi/lo
__global__ __launch_bounds__(256) void combine_kernel(
    const float* __restrict__ g, const float* __restrict__ u,
    bf16* __restrict__ hi, bf16* __restrict__ lo, int n4)
{
    for (int i = blockIdx.x * 256 + threadIdx.x; i < n4; i += gridDim.x * 256) {
        float4 gv = ((const float4*)g)[i];
        float4 uv = ((const float4*)u)[i];
        float a0 = (gv.x / (1.f + expf(-gv.x))) * uv.x;
        float a1 = (gv.y / (1.f + expf(-gv.y))) * uv.y;
        float a2 = (gv.z / (1.f + expf(-gv.z))) * uv.z;
        float a3 = (gv.w / (1.f + expf(-gv.w))) * uv.w;
        bf16 h0 = __float2bfloat16_rn(a0), h1 = __float2bfloat16_rn(a1);
        bf16 h2 = __float2bfloat16_rn(a2), h3 = __float2bfloat16_rn(a3);
        bf16 l0 = __float2bfloat16_rn(a0 - __bfloat162float(h0));
        bf16 l1 = __float2bfloat16_rn(a1 - __bfloat162float(h1));
        bf16 l2 = __float2bfloat16_rn(a2 - __bfloat162float(h2));
        bf16 l3 = __float2bfloat16_rn(a3 - __bfloat162float(h3));
        ((bf162*)hi)[2 * i]     = bf162(h0, h1);
        ((bf162*)hi)[2 * i + 1] = bf162(h2, h3);
        ((bf162*)lo)[2 * i]     = bf162(l0, l1);
        ((bf162*)lo)[2 * i + 1] = bf162(l2, l3);
    }
}

// ---------------------------------------------------------------------------
// Tensor-core GEMM: C(fp32) = Ahi*Bhi + Ahi*Blo + Alo*Bhi
// 128x128 CTA tile, 512 threads (16 warps, 4x4), warp tile 32x32, BK=32.
// GATHER: A rows gathered via g_tok (expert gate/up).
// AEXP:   A rows offset by e*T (expert down).
// EPI: 0 = store fp32 rows; 1 = expert-down scatter (xW into g_contrib);
//      2 = shared-down combine (sigmoid gate + contrib0 + contrib1 -> out)
// ---------------------------------------------------------------------------
__device__ __forceinline__ uint32_t smem_u32(const void* p) {
    return (uint32_t)__cvta_generic_to_shared(p);
}
__device__ __forceinline__ void ldsm_x4(uint32_t& r0, uint32_t& r1, uint32_t& r2, uint32_t& r3, uint32_t a) {
    asm volatile("ldmatrix.sync.aligned.m8n8.x4.shared.b16 {%0,%1,%2,%3}, [%4];"
                 : "=r"(r0), "=r"(r1), "=r"(r2), "=r"(r3) : "r"(a));
}
__device__ __forceinline__ void ldsm_x4_t(uint32_t& r0, uint32_t& r1, uint32_t& r2, uint32_t& r3, uint32_t a) {
    asm volatile("ldmatrix.sync.aligned.m8n8.x4.trans.shared.b16 {%0,%1,%2,%3}, [%4];"
                 : "=r"(r0), "=r"(r1), "=r"(r2), "=r"(r3) : "r"(a));
}
__device__ __forceinline__ void mma16816(float* d, const uint32_t* a, uint32_t b0, uint32_t b1) {
    asm volatile("mma.sync.aligned.m16n8k16.row.col.f32.bf16.bf16.f32 "
                 "{%0,%1,%2,%3}, {%4,%5,%6,%7}, {%8,%9}, {%0,%1,%2,%3};"
                 : "+f"(d[0]), "+f"(d[1]), "+f"(d[2]), "+f"(d[3])
                 : "r"(a[0]), "r"(a[1]), "r"(a[2]), "r"(a[3]), "r"(b0), "r"(b1));
}

template<int GATHER, int AEXP, int EPI>
__global__ __launch_bounds__(512, 1) void mma_gemm_kernel(
    const bf16* __restrict__ Ahi, const bf16* __restrict__ Alo,
    const bf16* __restrict__ Bhi, const bf16* __restrict__ Blo,
    float* __restrict__ outF, int K, int N)
{
    const int e  = blockIdx.z;
    const int m0 = blockIdx.y * 128;
    const int n0 = blockIdx.x * 128;
    const int cnt = (GATHER || AEXP) ? g_cnt[e] : T_TOKENS;
    if (m0 >= cnt) return;

    __shared__ bf16 AsHi[128][40];
    __shared__ bf16 AsLo[128][40];
    __shared__ bf16 BsHi[32][136];
    __shared__ bf16 BsLo[32][136];
    __shared__ int  s_tok[128];

    const int tid  = threadIdx.x;
    const int lane = tid & 31;
    const int warp = tid >> 5;
    const int wm = warp & 3;   // 0..3 -> m offset wm*32
    const int wn = warp >> 2;  // 0..3 -> n offset wn*32

    if (GATHER && tid < 128) {
        int gm = m0 + tid;
        s_tok[tid] = (gm < cnt) ? g_tok[e * T_TOKENS + gm] : 0;
    }
    __syncthreads();

    // A load mapping: 1024 uint2-chunks (128 rows x 8), 2 per thread
    const int ar0 = tid >> 3;            // 0..63
    const int ar1 = 64 + ar0;
    const int ak4 = (tid & 7) * 4;       // k offset in halves
    size_t aoff0, aoff1;
    if (GATHER) {
        aoff0 = (size_t)s_tok[ar0] * K;
        aoff1 = (size_t)s_tok[ar1] * K;
    } else {
        const size_t base = (size_t)m0 + (AEXP ? (size_t)e * T_TOKENS : 0);
        aoff0 = (base + ar0) * K;
        aoff1 = (base + ar1) * K;
    }

    // B load mapping: 512 uint4-chunks (32 rows x 16), 1 per thread
    const int brow = tid >> 4;           // 0..31
    const int bn8  = (tid & 15) * 8;
    const bf16* BhiE = Bhi + ((GATHER || AEXP) ? (size_t)e * K * N : 0);
    const bf16* BloE = Blo + ((GATHER || AEXP) ? (size_t)e * K * N : 0);

    float acc[2][4][4];
    #pragma unroll
    for (int i = 0; i < 2; ++i)
        #pragma unroll
        for (int j = 0; j < 4; ++j)
            #pragma unroll
            for (int v = 0; v < 4; ++v) acc[i][j][v] = 0.f;

    // ldmatrix per-lane addressing
    const int grp = lane >> 3;
    const int gl  = lane & 7;
    const int a_row_off = (grp & 1) * 8 + gl;   // within 16-row frag
    const int a_col_off = (grp >> 1) * 8;       // within 16-k frag
    const int b_row_off = (grp & 1) * 8 + gl;   // within 16-k frag
    const int b_col_off = (grp >> 1) * 8;       // within 16-n frag

    for (int k0 = 0; k0 < K; k0 += 32) {
        // load A tiles
        *(uint2*)&AsHi[ar0][ak4] = *(const uint2*)(Ahi + aoff0 + k0 + ak4);
        *(uint2*)&AsHi[ar1][ak4] = *(const uint2*)(Ahi + aoff1 + k0 + ak4);
        *(uint2*)&AsLo[ar0][ak4] = *(const uint2*)(Alo + aoff0 + k0 + ak4);
        *(uint2*)&AsLo[ar1][ak4] = *(const uint2*)(Alo + aoff1 + k0 + ak4);
        // load B tiles
        const size_t bgoff = (size_t)(k0 + brow) * N + n0 + bn8;
        *(uint4*)&BsHi[brow][bn8] = *(const uint4*)(BhiE + bgoff);
        *(uint4*)&BsLo[brow][bn8] = *(const uint4*)(BloE + bgoff);
        __syncthreads();

        #pragma unroll
        for (int ks = 0; ks < 32; ks += 16) {
            uint32_t ah[2][4], al[2][4];
            #pragma unroll
            for (int mi = 0; mi < 2; ++mi) {
                uint32_t addr = smem_u32(&AsHi[wm * 32 + mi * 16 + a_row_off][ks + a_col_off]);
                ldsm_x4(ah[mi][0], ah[mi][1], ah[mi][2], ah[mi][3], addr);
                addr = smem_u32(&AsLo[wm * 32 + mi * 16 + a_row_off][ks + a_col_off]);
                ldsm_x4(al[mi][0], al[mi][1], al[mi][2], al[mi][3], addr);
            }
            uint32_t bh[2][4], bl[2][4];
            #pragma unroll
            for (int g = 0; g < 2; ++g) {
                uint32_t addr = smem_u32(&BsHi[ks + b_row_off][wn * 32 + g * 16 + b_col_off]);
                ldsm_x4_t(bh[g][0], bh[g][1], bh[g][2], bh[g][3], addr);
                addr = smem_u32(&BsLo[ks + b_row_off][wn * 32 + g * 16 + b_col_off]);
                ldsm_x4_t(bl[g][0], bl[g][1], bl[g][2], bl[g][3], addr);
            }
            #pragma unroll
            for (int mi = 0; mi < 2; ++mi) {
                #pragma unroll
                for (int nj = 0; nj < 4; ++nj) {
                    const int g = nj >> 1, p = (nj & 1) * 2;
                    mma16816(acc[mi][nj], ah[mi], bh[g][p], bh[g][p + 1]);
                    mma16816(acc[mi][nj], ah[mi], bl[g][p], bl[g][p + 1]);
                    mma16816(acc[mi][nj], al[mi], bh[g][p], bh[g][p + 1]);
                }
            }
        }
        __syncthreads();
    }

    // Epilogue
    const int rbase = m0 + wm * 32 + (lane >> 2);
    const int cbase = n0 + wn * 32 + (lane & 3) * 2;

    #pragma unroll
    for (int mi = 0; mi < 2; ++mi) {
        #pragma unroll
        for (int half = 0; half < 2; ++half) {
            const int r = rbase + mi * 16 + half * 8;
            #pragma unroll
            for (int nj = 0; nj < 4; ++nj) {
                const int c = cbase + nj * 8;
                float v0 = acc[mi][nj][half * 2];
                float v1 = acc[mi][nj][half * 2 + 1];
                if (EPI == 0) {
                    const size_t orow = (size_t)((GATHER || AEXP) ? e * T_TOKENS : 0) + r;
                    float2 o = {v0, v1};
                    *(float2*)(outF + orow * N + c) = o;
                } else if (EPI == 1) {
                    if (r < cnt) {
                        const int idx = e * T_TOKENS + r;
                        const float w = g_wt[idx];
                        const int tok = g_tok[idx];
                        const int slot = g_slot[idx];
                        float2 o = {v0 * w, v1 * w};
                        *(float2*)(g_contrib + ((size_t)tok * 2 + slot) * H_DIM + c) = o;
                    }
                } else { // EPI == 2
                    const float sg = g_sgate[r];
                    const float2 c0 = *(const float2*)(g_contrib + ((size_t)r * 2 + 0) * H_DIM + c);
                    const float2 c1 = *(const float2*)(g_contrib + ((size_t)r * 2 + 1) * H_DIM + c);
                    float2 o = {sg * v0 + c0.x + c1.x, sg * v1 + c0.y + c1.y};
                    *(float2*)(outF + (size_t)r * H_DIM + c) = o;
                }
            }
        }
    }
}

// ---------------------------------------------------------------------------
extern "C" void kernel_launch(void* const* d_in, const int* in_sizes, int n_in,
                              void* d_out, int out_size)
{
    const float* hidden        = (const float*)d_in[0];
    const float* gate_w        = (const float*)d_in[1];
    const float* w_gate        = (const float*)d_in[2];
    const float* w_up          = (const float*)d_in[3];
    const float* w_down        = (const float*)d_in[4];
    const float* sw_gate       = (const float*)d_in[5];
    const float* sw_up         = (const float*)d_in[6];
    const float* sw_down       = (const float*)d_in[7];
    const float* shared_gate_w = (const float*)d_in[8];

    float* out        = (float*)d_out;
    float* out_logits = out + (size_t)T_TOKENS * H_DIM;

    bf16 *hidHi, *hidLo, *wgHi, *wgLo, *wuHi, *wuLo, *wdHi, *wdLo;
    bf16 *swgHi, *swgLo, *swuHi, *swuLo, *swdHi, *swdLo;
    bf16 *actHi, *actLo, *shHi, *shLo;
    float *tmpg, *tmpu;
    cudaGetSymbolAddress((void**)&hidHi, g_hid_hi);  cudaGetSymbolAddress((void**)&hidLo, g_hid_lo);
    cudaGetSymbolAddress((void**)&wgHi, g_wg_hi);    cudaGetSymbolAddress((void**)&wgLo, g_wg_lo);
    cudaGetSymbolAddress((void**)&wuHi, g_wu_hi);    cudaGetSymbolAddress((void**)&wuLo, g_wu_lo);
    cudaGetSymbolAddress((void**)&wdHi, g_wd_hi);    cudaGetSymbolAddress((void**)&wdLo, g_wd_lo);
    cudaGetSymbolAddress((void**)&swgHi, g_swg_hi);  cudaGetSymbolAddress((void**)&swgLo, g_swg_lo);
    cudaGetSymbolAddress((void**)&swuHi, g_swu_hi);  cudaGetSymbolAddress((void**)&swuLo, g_swu_lo);
    cudaGetSymbolAddress((void**)&swdHi, g_swd_hi);  cudaGetSymbolAddress((void**)&swdLo, g_swd_lo);
    cudaGetSymbolAddress((void**)&actHi, g_act_hi);  cudaGetSymbolAddress((void**)&actLo, g_act_lo);
    cudaGetSymbolAddress((void**)&shHi, g_shact_hi); cudaGetSymbolAddress((void**)&shLo, g_shact_lo);
    cudaGetSymbolAddress((void**)&tmpg, g_tmpg);     cudaGetSymbolAddress((void**)&tmpu, g_tmpu);

    // conversions (fp32 -> bf16 hi/lo)
    auto split = [&](const float* s, bf16* h, bf16* l, size_t n) {
        int n4 = (int)(n / 4);
        int grid = (n4 + 255) / 256; if (grid > 4096) grid = 4096;
        split_kernel<<<grid, 256>>>(s, h, l, n4);
    };
    split(hidden,  hidHi, hidLo, (size_t)T_TOKENS * H_DIM);
    split(w_gate,  wgHi,  wgLo,  (size_t)NE * H_DIM * I_DIM);
    split(w_up,    wuHi,  wuLo,  (size_t)NE * H_DIM * I_DIM);
    split(w_down,  wdHi,  wdLo,  (size_t)NE * I_DIM * H_DIM);
    split(sw_gate, swgHi, swgLo, (size_t)H_DIM * SI_DIM);
    split(sw_up,   swuHi, swuLo, (size_t)H_DIM * SI_DIM);
    split(sw_down, swdHi, swdLo, (size_t)SI_DIM * H_DIM);

    zero_cnt_kernel<<<1, 32>>>();
    router_kernel<<<T_TOKENS, 256>>>(hidden, gate_w, shared_gate_w, out_logits);

    // expert gate / up -> tmp buffers
    mma_gemm_kernel<1, 0, 0><<<dim3(I_DIM / 128, T_TOKENS / 128, NE), 512>>>(
        hidHi, hidLo, wgHi, wgLo, tmpg, H_DIM, I_DIM);
    mma_gemm_kernel<1, 0, 0><<<dim3(I_DIM / 128, T_TOKENS / 128, NE), 512>>>(
        hidHi, hidLo, wuHi, wuLo, tmpu, H_DIM, I_DIM);
    {
        int n4 = (int)((size_t)NE * T_TOKENS * I_DIM / 4);
        combine_kernel<<<4096, 256>>>(tmpg, tmpu, actHi, actLo, n4);
    }
    // expert down (scatter x routing weight)
    mma_gemm_kernel<0, 1, 1><<<dim3(H_DIM / 128, T_TOKENS / 128, NE), 512>>>(
        actHi, actLo, wdHi, wdLo, nullptr, I_DIM, H_DIM);

    // shared expert gate / up
    mma_gemm_kernel<0, 0, 0><<<dim3(SI_DIM / 128, T_TOKENS / 128, 1), 512>>>(
        hidHi, hidLo, swgHi, swgLo, tmpg, H_DIM, SI_DIM);
    mma_gemm_kernel<0, 0, 0><<<dim3(SI_DIM / 128, T_TOKENS / 128, 1), 512>>>(
        hidHi, hidLo, swuHi, swuLo, tmpu, H_DIM, SI_DIM);
    {
        int n4 = (int)((size_t)T_TOKENS * SI_DIM / 4);
        combine_kernel<<<4096, 256>>>(tmpg, tmpu, shHi, shLo, n4);
    }
    // shared down + final combine
    mma_gemm_kernel<0, 0, 2><<<dim3(H_DIM / 128, T_TOKENS / 128, 1), 512>>>(
        shHi, shLo, swdHi, swdLo, out, SI_DIM, H_DIM);
}

// round 5
// speedup vs baseline: 2.2234x; 1.2012x over previous
#include <cuda_runtime.h>
#include <cuda_bf16.h>
#include <math.h>
#include <stdint.h>

#define T_TOKENS 1024
#define H_DIM    2048
#define I_DIM    1408
#define SI_DIM   5632
#define NE       8

typedef __nv_bfloat16 bf16;
typedef __nv_bfloat162 bf162;

// ---------------------------------------------------------------------------
// Scratch (__device__ globals; no cudaMalloc allowed)
// ---------------------------------------------------------------------------
__device__ int   g_cnt[NE];
__device__ int   g_tok [NE * T_TOKENS];
__device__ int   g_slot[NE * T_TOKENS];
__device__ float g_wt  [NE * T_TOKENS];
__device__ float g_sgate[T_TOKENS];

__device__ bf16  g_act_hi[(size_t)NE * T_TOKENS * I_DIM];
__device__ bf16  g_act_lo[(size_t)NE * T_TOKENS * I_DIM];
__device__ bf16  g_shact_hi[(size_t)T_TOKENS * SI_DIM];
__device__ bf16  g_shact_lo[(size_t)T_TOKENS * SI_DIM];
__device__ float g_contrib[(size_t)T_TOKENS * 2 * H_DIM];

// ---------------------------------------------------------------------------
__global__ void zero_cnt_kernel() {
    if (threadIdx.x < NE) g_cnt[threadIdx.x] = 0;
}

// Router (fp32)
__global__ __launch_bounds__(256) void router_kernel(
    const float* __restrict__ hidden,
    const float* __restrict__ gate_w,
    const float* __restrict__ shared_gate_w,
    float* __restrict__ out_logits)
{
    const int t = blockIdx.x;
    __shared__ float sh[H_DIM];
    __shared__ float slog[NE];
    __shared__ float sred[256];

    const float* hrow = hidden + (size_t)t * H_DIM;
    for (int i = threadIdx.x; i < H_DIM; i += 256) sh[i] = hrow[i];
    __syncthreads();

    const int warp = threadIdx.x >> 5;
    const int lane = threadIdx.x & 31;

    float sum = 0.f;
    for (int k = lane; k < H_DIM; k += 32) sum += sh[k] * gate_w[k * NE + warp];
    #pragma unroll
    for (int o = 16; o; o >>= 1) sum += __shfl_down_sync(0xffffffffu, sum, o);
    if (lane == 0) slog[warp] = sum;

    float s2 = 0.f;
    for (int k = threadIdx.x; k < H_DIM; k += 256) s2 += sh[k] * shared_gate_w[k];
    sred[threadIdx.x] = s2;
    __syncthreads();
    for (int st = 128; st; st >>= 1) {
        if (threadIdx.x < st) sred[threadIdx.x] += sred[threadIdx.x + st];
        __syncthreads();
    }

    if (threadIdx.x == 0) {
        float lg[NE];
        float mx = -1e30f;
        #pragma unroll
        for (int e = 0; e < NE; ++e) { lg[e] = slog[e]; mx = fmaxf(mx, lg[e]); }
        float p[NE]; float den = 0.f;
        #pragma unroll
        for (int e = 0; e < NE; ++e) { p[e] = expf(lg[e] - mx); den += p[e]; }
        float inv = 1.f / den;
        #pragma unroll
        for (int e = 0; e < NE; ++e) {
            p[e] *= inv;
            out_logits[(size_t)t * NE + e] = lg[e];
        }
        int i0 = 0;
        #pragma unroll
        for (int e = 1; e < NE; ++e) if (p[e] > p[i0]) i0 = e;
        int i1 = -1;
        #pragma unroll
        for (int e = 0; e < NE; ++e) {
            if (e == i0) continue;
            if (i1 < 0 || p[e] > p[i1]) i1 = e;
        }
        int pos0 = atomicAdd(&g_cnt[i0], 1);
        g_tok [i0 * T_TOKENS + pos0] = t;
        g_slot[i0 * T_TOKENS + pos0] = 0;
        g_wt  [i0 * T_TOKENS + pos0] = p[i0];
        int pos1 = atomicAdd(&g_cnt[i1], 1);
        g_tok [i1 * T_TOKENS + pos1] = t;
        g_slot[i1 * T_TOKENS + pos1] = 1;
        g_wt  [i1 * T_TOKENS + pos1] = p[i1];

        g_sgate[t] = 1.f / (1.f + expf(-sred[0]));
    }
}

// ---------------------------------------------------------------------------
// helpers
// ---------------------------------------------------------------------------
__device__ __forceinline__ uint32_t smem_u32(const void* p) {
    return (uint32_t)__cvta_generic_to_shared(p);
}
__device__ __forceinline__ void ldsm_x4(uint32_t& r0, uint32_t& r1, uint32_t& r2, uint32_t& r3, uint32_t a) {
    asm volatile("ldmatrix.sync.aligned.m8n8.x4.shared.b16 {%0,%1,%2,%3}, [%4];"
                 : "=r"(r0), "=r"(r1), "=r"(r2), "=r"(r3) : "r"(a));
}
__device__ __forceinline__ void ldsm_x4_t(uint32_t& r0, uint32_t& r1, uint32_t& r2, uint32_t& r3, uint32_t a) {
    asm volatile("ldmatrix.sync.aligned.m8n8.x4.trans.shared.b16 {%0,%1,%2,%3}, [%4];"
                 : "=r"(r0), "=r"(r1), "=r"(r2), "=r"(r3) : "r"(a));
}
__device__ __forceinline__ void mma16816(float* d, const uint32_t* a, uint32_t b0, uint32_t b1) {
    asm volatile("mma.sync.aligned.m16n8k16.row.col.f32.bf16.bf16.f32 "
                 "{%0,%1,%2,%3}, {%4,%5,%6,%7}, {%8,%9}, {%0,%1,%2,%3};"
                 : "+f"(d[0]), "+f"(d[1]), "+f"(d[2]), "+f"(d[3])
                 : "r"(a[0]), "r"(a[1]), "r"(a[2]), "r"(a[3]), "r"(b0), "r"(b1));
}
// fp32x4 -> bf16 hi/lo packed pairs
__device__ __forceinline__ void split4(const float4& v, uint2& hi, uint2& lo) {
    bf16 h0 = __float2bfloat16_rn(v.x), h1 = __float2bfloat16_rn(v.y);
    bf16 h2 = __float2bfloat16_rn(v.z), h3 = __float2bfloat16_rn(v.w);
    bf162 H0(h0, h1), H1(h2, h3);
    bf162 L0(__float2bfloat16_rn(v.x - __bfloat162float(h0)),
             __float2bfloat16_rn(v.y - __bfloat162float(h1)));
    bf162 L1(__float2bfloat16_rn(v.z - __bfloat162float(h2)),
             __float2bfloat16_rn(v.w - __bfloat162float(h3)));
    hi.x = *reinterpret_cast<uint32_t*>(&H0); hi.y = *reinterpret_cast<uint32_t*>(&H1);
    lo.x = *reinterpret_cast<uint32_t*>(&L0); lo.y = *reinterpret_cast<uint32_t*>(&L1);
}
__device__ __forceinline__ void split2(float a, float b, uint32_t& hi, uint32_t& lo) {
    bf16 h0 = __float2bfloat16_rn(a), h1 = __float2bfloat16_rn(b);
    bf162 H(h0, h1);
    bf162 L(__float2bfloat16_rn(a - __bfloat162float(h0)),
            __float2bfloat16_rn(b - __bfloat162float(h1)));
    hi = *reinterpret_cast<uint32_t*>(&H);
    lo = *reinterpret_cast<uint32_t*>(&L);
}

// ---------------------------------------------------------------------------
// Fused dual-B gate+up GEMM, fp32 operands split to bf16 hi/lo in-kernel.
// 128(M) x 64(N) tile, 256 threads (8 warps: 4m x 2n), warp tile 32x32.
// C = Ahi*Bhi + Ahi*Blo + Alo*Bhi for both gate and up; epilogue
// silu(g)*u -> bf16 hi/lo written to out.
// GATHER=1: A rows via g_tok (expert e), B offset e*K*N, out rows e*T+m.
// ---------------------------------------------------------------------------
template<int GATHER>
__global__ __launch_bounds__(256, 1) void gateup_mma_kernel(
    const float* __restrict__ A,
    const float* __restrict__ Bg_, const float* __restrict__ Bu_,
    bf16* __restrict__ outHi, bf16* __restrict__ outLo,
    int K, int Ntot)
{
    const int e  = blockIdx.z;
    const int m0 = blockIdx.y * 128;
    const int n0 = blockIdx.x * 64;
    const int cnt = GATHER ? g_cnt[e] : T_TOKENS;
    if (m0 >= cnt) return;

    __shared__ bf16 AsHi[128][40];
    __shared__ bf16 AsLo[128][40];
    __shared__ bf16 BgHi[32][72];
    __shared__ bf16 BgLo[32][72];
    __shared__ bf16 BuHi[32][72];
    __shared__ bf16 BuLo[32][72];
    __shared__ int  s_tok[128];

    const int tid  = threadIdx.x;
    const int lane = tid & 31;
    const int warp = tid >> 5;
    const int wm = warp & 3;
    const int wn = warp >> 2;

    if (GATHER && tid < 128) {
        int gm = m0 + tid;
        s_tok[tid] = (gm < cnt) ? g_tok[e * T_TOKENS + gm] : 0;
    }
    __syncthreads();

    // A: 128 rows x 32 k fp32; 2 threads/row, 16 k each (4 float4)
    const int ar = tid >> 1;
    const int ac = (tid & 1) * 16;
    size_t arow_off;
    if (GATHER) arow_off = (size_t)s_tok[ar] * K;
    else        arow_off = (size_t)(m0 + ar) * K;

    // B: 32 rows x 64 n fp32 per matrix; 8 threads/row, 8 n each (2 float4)
    const int br = tid >> 3;
    const int bc = (tid & 7) * 8;
    const float* BgP = Bg_ + (GATHER ? (size_t)e * K * Ntot : 0) + n0 + bc;
    const float* BuP = Bu_ + (GATHER ? (size_t)e * K * Ntot : 0) + n0 + bc;

    float4 pa[4], pbg[2], pbu[2];
    auto load_regs = [&](int k0) {
        #pragma unroll
        for (int c = 0; c < 4; ++c) pa[c] = *(const float4*)(A + arow_off + k0 + ac + c * 4);
        #pragma unroll
        for (int c = 0; c < 2; ++c) {
            pbg[c] = *(const float4*)(BgP + (size_t)(k0 + br) * Ntot + c * 4);
            pbu[c] = *(const float4*)(BuP + (size_t)(k0 + br) * Ntot + c * 4);
        }
    };
    auto sts_regs = [&]() {
        #pragma unroll
        for (int c = 0; c < 4; ++c) {
            uint2 h, l; split4(pa[c], h, l);
            *(uint2*)&AsHi[ar][ac + c * 4] = h;
            *(uint2*)&AsLo[ar][ac + c * 4] = l;
        }
        #pragma unroll
        for (int c = 0; c < 2; ++c) {
            uint2 h, l;
            split4(pbg[c], h, l);
            *(uint2*)&BgHi[br][bc + c * 4] = h; *(uint2*)&BgLo[br][bc + c * 4] = l;
            split4(pbu[c], h, l);
            *(uint2*)&BuHi[br][bc + c * 4] = h; *(uint2*)&BuLo[br][bc + c * 4] = l;
        }
    };

    float accg[2][4][4], accu[2][4][4];
    #pragma unroll
    for (int i = 0; i < 2; ++i)
        #pragma unroll
        for (int j = 0; j < 4; ++j)
            #pragma unroll
            for (int v = 0; v < 4; ++v) { accg[i][j][v] = 0.f; accu[i][j][v] = 0.f; }

    const int grp = lane >> 3;
    const int gl  = lane & 7;
    const int a_row_off = (grp & 1) * 8 + gl;
    const int a_col_off = (grp >> 1) * 8;
    const int b_row_off = (grp & 1) * 8 + gl;
    const int b_col_off = (grp >> 1) * 8;

    load_regs(0);
    for (int k0 = 0; k0 < K; k0 += 32) {
        sts_regs();
        __syncthreads();
        if (k0 + 32 < K) load_regs(k0 + 32);

        #pragma unroll
        for (int ks = 0; ks < 32; ks += 16) {
            uint32_t ah[2][4], al[2][4];
            #pragma unroll
            for (int mi = 0; mi < 2; ++mi) {
                uint32_t addr = smem_u32(&AsHi[wm * 32 + mi * 16 + a_row_off][ks + a_col_off]);
                ldsm_x4(ah[mi][0], ah[mi][1], ah[mi][2], ah[mi][3], addr);
                addr = smem_u32(&AsLo[wm * 32 + mi * 16 + a_row_off][ks + a_col_off]);
                ldsm_x4(al[mi][0], al[mi][1], al[mi][2], al[mi][3], addr);
            }
            uint32_t gh[2][4], glo[2][4], uh[2][4], ulo[2][4];
            #pragma unroll
            for (int g = 0; g < 2; ++g) {
                uint32_t addr = smem_u32(&BgHi[ks + b_row_off][wn * 32 + g * 16 + b_col_off]);
                ldsm_x4_t(gh[g][0], gh[g][1], gh[g][2], gh[g][3], addr);
                addr = smem_u32(&BgLo[ks + b_row_off][wn * 32 + g * 16 + b_col_off]);
                ldsm_x4_t(glo[g][0], glo[g][1], glo[g][2], glo[g][3], addr);
                addr = smem_u32(&BuHi[ks + b_row_off][wn * 32 + g * 16 + b_col_off]);
                ldsm_x4_t(uh[g][0], uh[g][1], uh[g][2], uh[g][3], addr);
                addr = smem_u32(&BuLo[ks + b_row_off][wn * 32 + g * 16 + b_col_off]);
                ldsm_x4_t(ulo[g][0], ulo[g][1], ulo[g][2], ulo[g][3], addr);
            }
            #pragma unroll
            for (int mi = 0; mi < 2; ++mi) {
                #pragma unroll
                for (int nj = 0; nj < 4; ++nj) {
                    const int g = nj >> 1, p = (nj & 1) * 2;
                    mma16816(accg[mi][nj], ah[mi], gh[g][p], gh[g][p + 1]);
                    mma16816(accg[mi][nj], ah[mi], glo[g][p], glo[g][p + 1]);
                    mma16816(accg[mi][nj], al[mi], gh[g][p], gh[g][p + 1]);
                    mma16816(accu[mi][nj], ah[mi], uh[g][p], uh[g][p + 1]);
                    mma16816(accu[mi][nj], ah[mi], ulo[g][p], ulo[g][p + 1]);
                    mma16816(accu[mi][nj], al[mi], uh[g][p], uh[g][p + 1]);
                }
            }
        }
        __syncthreads();
    }

    // epilogue: silu(g)*u -> bf16 hi/lo
    const int rbase = m0 + wm * 32 + (lane >> 2);
    const int cbase = n0 + wn * 32 + (lane & 3) * 2;
    #pragma unroll
    for (int mi = 0; mi < 2; ++mi) {
        #pragma unroll
        for (int half = 0; half < 2; ++half) {
            const int r = rbase + mi * 16 + half * 8;
            const size_t row = (size_t)(GATHER ? e * T_TOKENS : 0) + r;
            #pragma unroll
            for (int nj = 0; nj < 4; ++nj) {
                const int c = cbase + nj * 8;
                float g0 = accg[mi][nj][half * 2],     u0 = accu[mi][nj][half * 2];
                float g1 = accg[mi][nj][half * 2 + 1], u1 = accu[mi][nj][half * 2 + 1];
                float a0 = (g0 / (1.f + expf(-g0))) * u0;
                float a1 = (g1 / (1.f + expf(-g1))) * u1;
                uint32_t hi, lo; split2(a0, a1, hi, lo);
                *(uint32_t*)(outHi + row * Ntot + c) = hi;
                *(uint32_t*)(outLo + row * Ntot + c) = lo;
            }
        }
    }
}

// ---------------------------------------------------------------------------
// Down GEMM: A bf16 hi/lo, B fp32 (split in-kernel).
// 128x128 tile, 512 threads (16 warps 4x4), warp tile 32x32.
// EPI=1: expert scatter (x routing weight into g_contrib)
// EPI=2: shared combine (sigmoid gate + contrib -> out)
// ---------------------------------------------------------------------------
template<int AEXP, int EPI>
__global__ __launch_bounds__(512, 1) void down_mma_kernel(
    const bf16* __restrict__ Ahi, const bf16* __restrict__ Alo,
    const float* __restrict__ B_,
    float* __restrict__ outF, int K, int N)
{
    const int e  = blockIdx.z;
    const int m0 = blockIdx.y * 128;
    const int n0 = blockIdx.x * 128;
    const int cnt = AEXP ? g_cnt[e] : T_TOKENS;
    if (m0 >= cnt) return;

    __shared__ bf16 AsHi[128][40];
    __shared__ bf16 AsLo[128][40];
    __shared__ bf16 BsHi[32][136];
    __shared__ bf16 BsLo[32][136];

    const int tid  = threadIdx.x;
    const int lane = tid & 31;
    const int warp = tid >> 5;
    const int wm = warp & 3;
    const int wn = warp >> 2;

    // A: bf16 hi/lo, 128 rows x 32 k; 8 threads/row-pair mapping (as before)
    const int ar0 = tid >> 3;
    const int ar1 = 64 + ar0;
    const int ak4 = (tid & 7) * 4;
    const size_t abase = (size_t)m0 + (AEXP ? (size_t)e * T_TOKENS : 0);
    const size_t aoff0 = (abase + ar0) * K;
    const size_t aoff1 = (abase + ar1) * K;

    // B: fp32 32 x 128; 16 threads/row, 8 n each (2 float4)
    const int brow = tid >> 4;
    const int bcol = (tid & 15) * 8;
    const float* BP = B_ + (AEXP ? (size_t)e * K * N : 0) + n0 + bcol;

    uint2  pa[4];
    float4 pb[2];
    auto load_regs = [&](int k0) {
        pa[0] = *(const uint2*)(Ahi + aoff0 + k0 + ak4);
        pa[1] = *(const uint2*)(Ahi + aoff1 + k0 + ak4);
        pa[2] = *(const uint2*)(Alo + aoff0 + k0 + ak4);
        pa[3] = *(const uint2*)(Alo + aoff1 + k0 + ak4);
        pb[0] = *(const float4*)(BP + (size_t)(k0 + brow) * N);
        pb[1] = *(const float4*)(BP + (size_t)(k0 + brow) * N + 4);
    };
    auto sts_regs = [&]() {
        *(uint2*)&AsHi[ar0][ak4] = pa[0];
        *(uint2*)&AsHi[ar1][ak4] = pa[1];
        *(uint2*)&AsLo[ar0][ak4] = pa[2];
        *(uint2*)&AsLo[ar1][ak4] = pa[3];
        uint2 h, l;
        split4(pb[0], h, l);
        *(uint2*)&BsHi[brow][bcol] = h; *(uint2*)&BsLo[brow][bcol] = l;
        split4(pb[1], h, l);
        *(uint2*)&BsHi[brow][bcol + 4] = h; *(uint2*)&BsLo[brow][bcol + 4] = l;
    };

    float acc[2][4][4];
    #pragma unroll
    for (int i = 0; i < 2; ++i)
        #pragma unroll
        for (int j = 0; j < 4; ++j)
            #pragma unroll
            for (int v = 0; v < 4; ++v) acc[i][j][v] = 0.f;

    const int grp = lane >> 3;
    const int gl  = lane & 7;
    const int a_row_off = (grp & 1) * 8 + gl;
    const int a_col_off = (grp >> 1) * 8;
    const int b_row_off = (grp & 1) * 8 + gl;
    const int b_col_off = (grp >> 1) * 8;

    load_regs(0);
    for (int k0 = 0; k0 < K; k0 += 32) {
        sts_regs();
        __syncthreads();
        if (k0 + 32 < K) load_regs(k0 + 32);

        #pragma unroll
        for (int ks = 0; ks < 32; ks += 16) {
            uint32_t ah[2][4], al[2][4];
            #pragma unroll
            for (int mi = 0; mi < 2; ++mi) {
                uint32_t addr = smem_u32(&AsHi[wm * 32 + mi * 16 + a_row_off][ks + a_col_off]);
                ldsm_x4(ah[mi][0], ah[mi][1], ah[mi][2], ah[mi][3], addr);
                addr = smem_u32(&AsLo[wm * 32 + mi * 16 + a_row_off][ks + a_col_off]);
                ldsm_x4(al[mi][0], al[mi][1], al[mi][2], al[mi][3], addr);
            }
            uint32_t bh[2][4], bl[2][4];
            #pragma unroll
            for (int g = 0; g < 2; ++g) {
                uint32_t addr = smem_u32(&BsHi[ks + b_row_off][wn * 32 + g * 16 + b_col_off]);
                ldsm_x4_t(bh[g][0], bh[g][1], bh[g][2], bh[g][3], addr);
                addr = smem_u32(&BsLo[ks + b_row_off][wn * 32 + g * 16 + b_col_off]);
                ldsm_x4_t(bl[g][0], bl[g][1], bl[g][2], bl[g][3], addr);
            }
            #pragma unroll
            for (int mi = 0; mi < 2; ++mi) {
                #pragma unroll
                for (int nj = 0; nj < 4; ++nj) {
                    const int g = nj >> 1, p = (nj & 1) * 2;
                    mma16816(acc[mi][nj], ah[mi], bh[g][p], bh[g][p + 1]);
                    mma16816(acc[mi][nj], ah[mi], bl[g][p], bl[g][p + 1]);
                    mma16816(acc[mi][nj], al[mi], bh[g][p], bh[g][p + 1]);
                }
            }
        }
        __syncthreads();
    }

    const int rbase = m0 + wm * 32 + (lane >> 2);
    const int cbase = n0 + wn * 32 + (lane & 3) * 2;
    #pragma unroll
    for (int mi = 0; mi < 2; ++mi) {
        #pragma unroll
        for (int half = 0; half < 2; ++half) {
            const int r = rbase + mi * 16 + half * 8;
            #pragma unroll
            for (int nj = 0; nj < 4; ++nj) {
                const int c = cbase + nj * 8;
                float v0 = acc[mi][nj][half * 2];
                float v1 = acc[mi][nj][half * 2 + 1];
                if (EPI == 1) {
                    if (r < cnt) {
                        const int idx = e * T_TOKENS + r;
                        const float w = g_wt[idx];
                        const int tok = g_tok[idx];
                        const int slot = g_slot[idx];
                        float2 o = {v0 * w, v1 * w};
                        *(float2*)(g_contrib + ((size_t)tok * 2 + slot) * H_DIM + c) = o;
                    }
                } else {
                    const float sg = g_sgate[r];
                    const float2 c0 = *(const float2*)(g_contrib + ((size_t)r * 2 + 0) * H_DIM + c);
                    const float2 c1 = *(const float2*)(g_contrib + ((size_t)r * 2 + 1) * H_DIM + c);
                    float2 o = {sg * v0 + c0.x + c1.x, sg * v1 + c0.y + c1.y};
                    *(float2*)(outF + (size_t)r * H_DIM + c) = o;
                }
            }
        }
    }
}

// ---------------------------------------------------------------------------
extern "C" void kernel_launch(void* const* d_in, const int* in_sizes, int n_in,
                              void* d_out, int out_size)
{
    const float* hidden        = (const float*)d_in[0];
    const float* gate_w        = (const float*)d_in[1];
    const float* w_gate        = (const float*)d_in[2];
    const float* w_up          = (const float*)d_in[3];
    const float* w_down        = (const float*)d_in[4];
    const float* sw_gate       = (const float*)d_in[5];
    const float* sw_up         = (const float*)d_in[6];
    const float* sw_down       = (const float*)d_in[7];
    const float* shared_gate_w = (const float*)d_in[8];

    float* out        = (float*)d_out;
    float* out_logits = out + (size_t)T_TOKENS * H_DIM;

    bf16 *actHi, *actLo, *shHi, *shLo;
    cudaGetSymbolAddress((void**)&actHi, g_act_hi);
    cudaGetSymbolAddress((void**)&actLo, g_act_lo);
    cudaGetSymbolAddress((void**)&shHi, g_shact_hi);
    cudaGetSymbolAddress((void**)&shLo, g_shact_lo);

    zero_cnt_kernel<<<1, 32>>>();
    router_kernel<<<T_TOKENS, 256>>>(hidden, gate_w, shared_gate_w, out_logits);

    // expert gate+up fused -> act hi/lo
    gateup_mma_kernel<1><<<dim3(I_DIM / 64, T_TOKENS / 128, NE), 256>>>(
        hidden, w_gate, w_up, actHi, actLo, H_DIM, I_DIM);
    // expert down (scatter x routing weight)
    down_mma_kernel<1, 1><<<dim3(H_DIM / 128, T_TOKENS / 128, NE), 512>>>(
        actHi, actLo, w_down, nullptr, I_DIM, H_DIM);

    // shared gate+up fused -> shact hi/lo
    gateup_mma_kernel<0><<<dim3(SI_DIM / 64, T_TOKENS / 128, 1), 256>>>(
        hidden, sw_gate, sw_up, shHi, shLo, H_DIM, SI_DIM);
    // shared down + final combine
    down_mma_kernel<0, 2><<<dim3(H_DIM / 128, T_TOKENS / 128, 1), 512>>>(
        shHi, shLo, sw_down, out, SI_DIM, H_DIM);
}

// round 6
// speedup vs baseline: 2.3206x; 1.0437x over previous
#include <cuda_runtime.h>
#include <cuda_bf16.h>
#include <math.h>
#include <stdint.h>

#define T_TOKENS 1024
#define H_DIM    2048
#define I_DIM    1408
#define SI_DIM   5632
#define NE       8

typedef __nv_bfloat16 bf16;
typedef __nv_bfloat162 bf162;

// ---------------------------------------------------------------------------
// Scratch (__device__ globals; no cudaMalloc allowed)
// ---------------------------------------------------------------------------
__device__ int   g_cnt[NE];
__device__ int   g_tok [NE * T_TOKENS];
__device__ int   g_slot[NE * T_TOKENS];
__device__ float g_wt  [NE * T_TOKENS];
__device__ float g_sgate[T_TOKENS];

__device__ bf16  g_act_hi[(size_t)NE * T_TOKENS * I_DIM];
__device__ bf16  g_act_lo[(size_t)NE * T_TOKENS * I_DIM];
__device__ bf16  g_shact_hi[(size_t)T_TOKENS * SI_DIM];
__device__ bf16  g_shact_lo[(size_t)T_TOKENS * SI_DIM];
__device__ float g_contrib[(size_t)T_TOKENS * 2 * H_DIM];

// ---------------------------------------------------------------------------
__global__ void zero_cnt_kernel() {
    if (threadIdx.x < NE) g_cnt[threadIdx.x] = 0;
}

// Router (fp32)
__global__ __launch_bounds__(256) void router_kernel(
    const float* __restrict__ hidden,
    const float* __restrict__ gate_w,
    const float* __restrict__ shared_gate_w,
    float* __restrict__ out_logits)
{
    const int t = blockIdx.x;
    __shared__ float sh[H_DIM];
    __shared__ float slog[NE];
    __shared__ float sred[256];

    const float* hrow = hidden + (size_t)t * H_DIM;
    for (int i = threadIdx.x; i < H_DIM; i += 256) sh[i] = hrow[i];
    __syncthreads();

    const int warp = threadIdx.x >> 5;
    const int lane = threadIdx.x & 31;

    float sum = 0.f;
    for (int k = lane; k < H_DIM; k += 32) sum += sh[k] * gate_w[k * NE + warp];
    #pragma unroll
    for (int o = 16; o; o >>= 1) sum += __shfl_down_sync(0xffffffffu, sum, o);
    if (lane == 0) slog[warp] = sum;

    float s2 = 0.f;
    for (int k = threadIdx.x; k < H_DIM; k += 256) s2 += sh[k] * shared_gate_w[k];
    sred[threadIdx.x] = s2;
    __syncthreads();
    for (int st = 128; st; st >>= 1) {
        if (threadIdx.x < st) sred[threadIdx.x] += sred[threadIdx.x + st];
        __syncthreads();
    }

    if (threadIdx.x == 0) {
        float lg[NE];
        float mx = -1e30f;
        #pragma unroll
        for (int e = 0; e < NE; ++e) { lg[e] = slog[e]; mx = fmaxf(mx, lg[e]); }
        float p[NE]; float den = 0.f;
        #pragma unroll
        for (int e = 0; e < NE; ++e) { p[e] = expf(lg[e] - mx); den += p[e]; }
        float inv = 1.f / den;
        #pragma unroll
        for (int e = 0; e < NE; ++e) {
            p[e] *= inv;
            out_logits[(size_t)t * NE + e] = lg[e];
        }
        int i0 = 0;
        #pragma unroll
        for (int e = 1; e < NE; ++e) if (p[e] > p[i0]) i0 = e;
        int i1 = -1;
        #pragma unroll
        for (int e = 0; e < NE; ++e) {
            if (e == i0) continue;
            if (i1 < 0 || p[e] > p[i1]) i1 = e;
        }
        int pos0 = atomicAdd(&g_cnt[i0], 1);
        g_tok [i0 * T_TOKENS + pos0] = t;
        g_slot[i0 * T_TOKENS + pos0] = 0;
        g_wt  [i0 * T_TOKENS + pos0] = p[i0];
        int pos1 = atomicAdd(&g_cnt[i1], 1);
        g_tok [i1 * T_TOKENS + pos1] = t;
        g_slot[i1 * T_TOKENS + pos1] = 1;
        g_wt  [i1 * T_TOKENS + pos1] = p[i1];

        g_sgate[t] = 1.f / (1.f + expf(-sred[0]));
    }
}

// ---------------------------------------------------------------------------
// helpers
// ---------------------------------------------------------------------------
__device__ __forceinline__ uint32_t smem_u32(const void* p) {
    return (uint32_t)__cvta_generic_to_shared(p);
}
__device__ __forceinline__ void ldsm_x4(uint32_t& r0, uint32_t& r1, uint32_t& r2, uint32_t& r3, uint32_t a) {
    asm volatile("ldmatrix.sync.aligned.m8n8.x4.shared.b16 {%0,%1,%2,%3}, [%4];"
                 : "=r"(r0), "=r"(r1), "=r"(r2), "=r"(r3) : "r"(a));
}
__device__ __forceinline__ void ldsm_x4_t(uint32_t& r0, uint32_t& r1, uint32_t& r2, uint32_t& r3, uint32_t a) {
    asm volatile("ldmatrix.sync.aligned.m8n8.x4.trans.shared.b16 {%0,%1,%2,%3}, [%4];"
                 : "=r"(r0), "=r"(r1), "=r"(r2), "=r"(r3) : "r"(a));
}
__device__ __forceinline__ void mma16816(float* d, const uint32_t* a, uint32_t b0, uint32_t b1) {
    asm volatile("mma.sync.aligned.m16n8k16.row.col.f32.bf16.bf16.f32 "
                 "{%0,%1,%2,%3}, {%4,%5,%6,%7}, {%8,%9}, {%0,%1,%2,%3};"
                 : "+f"(d[0]), "+f"(d[1]), "+f"(d[2]), "+f"(d[3])
                 : "r"(a[0]), "r"(a[1]), "r"(a[2]), "r"(a[3]), "r"(b0), "r"(b1));
}
__device__ __forceinline__ void split4(const float4& v, uint2& hi, uint2& lo) {
    bf16 h0 = __float2bfloat16_rn(v.x), h1 = __float2bfloat16_rn(v.y);
    bf16 h2 = __float2bfloat16_rn(v.z), h3 = __float2bfloat16_rn(v.w);
    bf162 H0(h0, h1), H1(h2, h3);
    bf162 L0(__float2bfloat16_rn(v.x - __bfloat162float(h0)),
             __float2bfloat16_rn(v.y - __bfloat162float(h1)));
    bf162 L1(__float2bfloat16_rn(v.z - __bfloat162float(h2)),
             __float2bfloat16_rn(v.w - __bfloat162float(h3)));
    hi.x = *reinterpret_cast<uint32_t*>(&H0); hi.y = *reinterpret_cast<uint32_t*>(&H1);
    lo.x = *reinterpret_cast<uint32_t*>(&L0); lo.y = *reinterpret_cast<uint32_t*>(&L1);
}
__device__ __forceinline__ void split2(float a, float b, uint32_t& hi, uint32_t& lo) {
    bf16 h0 = __float2bfloat16_rn(a), h1 = __float2bfloat16_rn(b);
    bf162 H(h0, h1);
    bf162 L(__float2bfloat16_rn(a - __bfloat162float(h0)),
            __float2bfloat16_rn(b - __bfloat162float(h1)));
    hi = *reinterpret_cast<uint32_t*>(&H);
    lo = *reinterpret_cast<uint32_t*>(&L);
}

// ---------------------------------------------------------------------------
// Fused dual-B gate+up GEMM (warp-split across matrices).
// Tile 64(M) x 64(N per matrix). 256 threads = 8 warps: 2m x 2n x 2(matrix).
// Each warp computes a 32x32 tile of EITHER gate or up; epilogue exchanges
// up-accumulators through smem, g-warps apply silu(g)*u -> bf16 hi/lo.
// ---------------------------------------------------------------------------
template<int GATHER>
__global__ __launch_bounds__(256, 2) void gateup_mma_kernel(
    const float* __restrict__ A,
    const float* __restrict__ Bg_, const float* __restrict__ Bu_,
    bf16* __restrict__ outHi, bf16* __restrict__ outLo,
    int K, int Ntot)
{
    const int e  = blockIdx.z;
    const int m0 = blockIdx.y * 64;
    const int n0 = blockIdx.x * 64;
    const int cnt = GATHER ? g_cnt[e] : T_TOKENS;
    if (m0 >= cnt) return;

    __shared__ bf16 AsHi[64][40];
    __shared__ bf16 AsLo[64][40];
    __shared__ bf16 BgHi[32][72];
    __shared__ bf16 BgLo[32][72];
    __shared__ bf16 BuHi[32][72];
    __shared__ bf16 BuLo[32][72];
    __shared__ float exch[64][72];
    __shared__ int  s_tok[64];

    const int tid  = threadIdx.x;
    const int lane = tid & 31;
    const int warp = tid >> 5;
    const int wm   = warp & 1;
    const int wn   = (warp >> 1) & 1;
    const int wmat = warp >> 2;          // 0=gate, 1=up

    if (GATHER && tid < 64) {
        int gm = m0 + tid;
        s_tok[tid] = (gm < cnt) ? g_tok[e * T_TOKENS + gm] : 0;
    }
    __syncthreads();

    // A: 64 rows x 32 k fp32; 4 threads/row, 8 k each
    const int ar = tid >> 2;
    const int ac = (tid & 3) * 8;
    size_t arow_off;
    if (GATHER) arow_off = (size_t)s_tok[ar] * K;
    else        arow_off = (size_t)(m0 + ar) * K;

    // B: 32 rows x 64 n per matrix; 8 threads/row, 8 n each
    const int br = tid >> 3;
    const int bc = (tid & 7) * 8;
    const float* BgP = Bg_ + (GATHER ? (size_t)e * K * Ntot : 0) + n0 + bc;
    const float* BuP = Bu_ + (GATHER ? (size_t)e * K * Ntot : 0) + n0 + bc;

    float4 pa[2], pbg[2], pbu[2];
    auto load_regs = [&](int k0) {
        #pragma unroll
        for (int c = 0; c < 2; ++c) pa[c] = *(const float4*)(A + arow_off + k0 + ac + c * 4);
        #pragma unroll
        for (int c = 0; c < 2; ++c) {
            pbg[c] = *(const float4*)(BgP + (size_t)(k0 + br) * Ntot + c * 4);
            pbu[c] = *(const float4*)(BuP + (size_t)(k0 + br) * Ntot + c * 4);
        }
    };
    auto sts_regs = [&]() {
        #pragma unroll
        for (int c = 0; c < 2; ++c) {
            uint2 h, l; split4(pa[c], h, l);
            *(uint2*)&AsHi[ar][ac + c * 4] = h;
            *(uint2*)&AsLo[ar][ac + c * 4] = l;
        }
        #pragma unroll
        for (int c = 0; c < 2; ++c) {
            uint2 h, l;
            split4(pbg[c], h, l);
            *(uint2*)&BgHi[br][bc + c * 4] = h; *(uint2*)&BgLo[br][bc + c * 4] = l;
            split4(pbu[c], h, l);
            *(uint2*)&BuHi[br][bc + c * 4] = h; *(uint2*)&BuLo[br][bc + c * 4] = l;
        }
    };

    float acc[2][4][4];
    #pragma unroll
    for (int i = 0; i < 2; ++i)
        #pragma unroll
        for (int j = 0; j < 4; ++j)
            #pragma unroll
            for (int v = 0; v < 4; ++v) acc[i][j][v] = 0.f;

    const int grp = lane >> 3;
    const int gl  = lane & 7;
    const int a_row_off = (grp & 1) * 8 + gl;
    const int a_col_off = (grp >> 1) * 8;
    const int b_row_off = (grp & 1) * 8 + gl;
    const int b_col_off = (grp >> 1) * 8;

    bf16 (*BH)[72] = wmat ? BuHi : BgHi;
    bf16 (*BL)[72] = wmat ? BuLo : BgLo;

    load_regs(0);
    for (int k0 = 0; k0 < K; k0 += 32) {
        sts_regs();
        __syncthreads();
        if (k0 + 32 < K) load_regs(k0 + 32);

        #pragma unroll
        for (int ks = 0; ks < 32; ks += 16) {
            uint32_t ah[2][4], al[2][4];
            #pragma unroll
            for (int mi = 0; mi < 2; ++mi) {
                uint32_t addr = smem_u32(&AsHi[wm * 32 + mi * 16 + a_row_off][ks + a_col_off]);
                ldsm_x4(ah[mi][0], ah[mi][1], ah[mi][2], ah[mi][3], addr);
                addr = smem_u32(&AsLo[wm * 32 + mi * 16 + a_row_off][ks + a_col_off]);
                ldsm_x4(al[mi][0], al[mi][1], al[mi][2], al[mi][3], addr);
            }
            uint32_t bh[2][4], bl[2][4];
            #pragma unroll
            for (int g = 0; g < 2; ++g) {
                uint32_t addr = smem_u32(&BH[ks + b_row_off][wn * 32 + g * 16 + b_col_off]);
                ldsm_x4_t(bh[g][0], bh[g][1], bh[g][2], bh[g][3], addr);
                addr = smem_u32(&BL[ks + b_row_off][wn * 32 + g * 16 + b_col_off]);
                ldsm_x4_t(bl[g][0], bl[g][1], bl[g][2], bl[g][3], addr);
            }
            #pragma unroll
            for (int mi = 0; mi < 2; ++mi) {
                #pragma unroll
                for (int nj = 0; nj < 4; ++nj) {
                    const int g = nj >> 1, p = (nj & 1) * 2;
                    mma16816(acc[mi][nj], ah[mi], bh[g][p], bh[g][p + 1]);
                    mma16816(acc[mi][nj], ah[mi], bl[g][p], bl[g][p + 1]);
                    mma16816(acc[mi][nj], al[mi], bh[g][p], bh[g][p + 1]);
                }
            }
        }
        __syncthreads();
    }

    // epilogue: u-warps publish, g-warps combine
    const int rl_base = wm * 32 + (lane >> 2);
    const int cl_base = wn * 32 + (lane & 3) * 2;

    if (wmat == 1) {
        #pragma unroll
        for (int mi = 0; mi < 2; ++mi)
            #pragma unroll
            for (int half = 0; half < 2; ++half) {
                const int rl = rl_base + mi * 16 + half * 8;
                #pragma unroll
                for (int nj = 0; nj < 4; ++nj) {
                    const int cl = cl_base + nj * 8;
                    exch[rl][cl]     = acc[mi][nj][half * 2];
                    exch[rl][cl + 1] = acc[mi][nj][half * 2 + 1];
                }
            }
    }
    __syncthreads();
    if (wmat == 0) {
        #pragma unroll
        for (int mi = 0; mi < 2; ++mi)
            #pragma unroll
            for (int half = 0; half < 2; ++half) {
                const int rl = rl_base + mi * 16 + half * 8;
                const int r = m0 + rl;
                if (GATHER && r >= cnt) continue;
                const size_t row = (size_t)(GATHER ? e * T_TOKENS : 0) + r;
                #pragma unroll
                for (int nj = 0; nj < 4; ++nj) {
                    const int cl = cl_base + nj * 8;
                    float g0 = acc[mi][nj][half * 2];
                    float g1 = acc[mi][nj][half * 2 + 1];
                    float u0 = exch[rl][cl];
                    float u1 = exch[rl][cl + 1];
                    float a0 = (g0 / (1.f + expf(-g0))) * u0;
                    float a1 = (g1 / (1.f + expf(-g1))) * u1;
                    uint32_t hi, lo; split2(a0, a1, hi, lo);
                    *(uint32_t*)(outHi + row * Ntot + n0 + cl) = hi;
                    *(uint32_t*)(outLo + row * Ntot + n0 + cl) = lo;
                }
            }
    }
}

// ---------------------------------------------------------------------------
// Down GEMM: A bf16 hi/lo, B fp32 (split in-kernel).
// Tile 128(M) x 64(N), 256 threads = 8 warps (4m x 2n), warp tile 32x32.
// EPI=1: expert scatter (x routing weight into g_contrib)
// EPI=2: shared combine (sigmoid gate + contrib -> out)
// ---------------------------------------------------------------------------
template<int AEXP, int EPI>
__global__ __launch_bounds__(256, 2) void down_mma_kernel(
    const bf16* __restrict__ Ahi, const bf16* __restrict__ Alo,
    const float* __restrict__ B_,
    float* __restrict__ outF, int K, int N)
{
    const int e  = blockIdx.z;
    const int m0 = blockIdx.y * 128;
    const int n0 = blockIdx.x * 64;
    const int cnt = AEXP ? g_cnt[e] : T_TOKENS;
    if (m0 >= cnt) return;

    __shared__ bf16 AsHi[128][40];
    __shared__ bf16 AsLo[128][40];
    __shared__ bf16 BsHi[32][72];
    __shared__ bf16 BsLo[32][72];

    const int tid  = threadIdx.x;
    const int lane = tid & 31;
    const int warp = tid >> 5;
    const int wm = warp & 3;
    const int wn = warp >> 2;

    // A: 128 rows x 32 k halves; 2 threads/row, 16 halves each (uint4 x2)
    const int ar = tid >> 1;
    const int ac = (tid & 1) * 16;
    const size_t abase = (size_t)m0 + (AEXP ? (size_t)e * T_TOKENS : 0);
    const size_t aoff = (abase + ar) * K;

    // B: fp32 32 x 64; 8 threads/row, 8 n each
    const int br = tid >> 3;
    const int bc = (tid & 7) * 8;
    const float* BP = B_ + (AEXP ? (size_t)e * K * N : 0) + n0 + bc;

    uint4  pah[2], pal[2];
    float4 pb[2];
    auto load_regs = [&](int k0) {
        pah[0] = *(const uint4*)(Ahi + aoff + k0 + ac);
        pah[1] = *(const uint4*)(Ahi + aoff + k0 + ac + 8);
        pal[0] = *(const uint4*)(Alo + aoff + k0 + ac);
        pal[1] = *(const uint4*)(Alo + aoff + k0 + ac + 8);
        pb[0] = *(const float4*)(BP + (size_t)(k0 + br) * N);
        pb[1] = *(const float4*)(BP + (size_t)(k0 + br) * N + 4);
    };
    auto sts_regs = [&]() {
        *(uint4*)&AsHi[ar][ac]     = pah[0];
        *(uint4*)&AsHi[ar][ac + 8] = pah[1];
        *(uint4*)&AsLo[ar][ac]     = pal[0];
        *(uint4*)&AsLo[ar][ac + 8] = pal[1];
        uint2 h, l;
        split4(pb[0], h, l);
        *(uint2*)&BsHi[br][bc] = h; *(uint2*)&BsLo[br][bc] = l;
        split4(pb[1], h, l);
        *(uint2*)&BsHi[br][bc + 4] = h; *(uint2*)&BsLo[br][bc + 4] = l;
    };

    float acc[2][4][4];
    #pragma unroll
    for (int i = 0; i < 2; ++i)
        #pragma unroll
        for (int j = 0; j < 4; ++j)
            #pragma unroll
            for (int v = 0; v < 4; ++v) acc[i][j][v] = 0.f;

    const int grp = lane >> 3;
    const int gl  = lane & 7;
    const int a_row_off = (grp & 1) * 8 + gl;
    const int a_col_off = (grp >> 1) * 8;
    const int b_row_off = (grp & 1) * 8 + gl;
    const int b_col_off = (grp >> 1) * 8;

    load_regs(0);
    for (int k0 = 0; k0 < K; k0 += 32) {
        sts_regs();
        __syncthreads();
        if (k0 + 32 < K) load_regs(k0 + 32);

        #pragma unroll
        for (int ks = 0; ks < 32; ks += 16) {
            uint32_t ah[2][4], al[2][4];
            #pragma unroll
            for (int mi = 0; mi < 2; ++mi) {
                uint32_t addr = smem_u32(&AsHi[wm * 32 + mi * 16 + a_row_off][ks + a_col_off]);
                ldsm_x4(ah[mi][0], ah[mi][1], ah[mi][2], ah[mi][3], addr);
                addr = smem_u32(&AsLo[wm * 32 + mi * 16 + a_row_off][ks + a_col_off]);
                ldsm_x4(al[mi][0], al[mi][1], al[mi][2], al[mi][3], addr);
            }
            uint32_t bh[2][4], bl[2][4];
            #pragma unroll
            for (int g = 0; g < 2; ++g) {
                uint32_t addr = smem_u32(&BsHi[ks + b_row_off][wn * 32 + g * 16 + b_col_off]);
                ldsm_x4_t(bh[g][0], bh[g][1], bh[g][2], bh[g][3], addr);
                addr = smem_u32(&BsLo[ks + b_row_off][wn * 32 + g * 16 + b_col_off]);
                ldsm_x4_t(bl[g][0], bl[g][1], bl[g][2], bl[g][3], addr);
            }
            #pragma unroll
            for (int mi = 0; mi < 2; ++mi) {
                #pragma unroll
                for (int nj = 0; nj < 4; ++nj) {
                    const int g = nj >> 1, p = (nj & 1) * 2;
                    mma16816(acc[mi][nj], ah[mi], bh[g][p], bh[g][p + 1]);
                    mma16816(acc[mi][nj], ah[mi], bl[g][p], bl[g][p + 1]);
                    mma16816(acc[mi][nj], al[mi], bh[g][p], bh[g][p + 1]);
                }
            }
        }
        __syncthreads();
    }

    const int rbase = m0 + wm * 32 + (lane >> 2);
    const int cbase = n0 + wn * 32 + (lane & 3) * 2;
    #pragma unroll
    for (int mi = 0; mi < 2; ++mi) {
        #pragma unroll
        for (int half = 0; half < 2; ++half) {
            const int r = rbase + mi * 16 + half * 8;
            #pragma unroll
            for (int nj = 0; nj < 4; ++nj) {
                const int c = cbase + nj * 8;
                float v0 = acc[mi][nj][half * 2];
                float v1 = acc[mi][nj][half * 2 + 1];
                if (EPI == 1) {
                    if (r < cnt) {
                        const int idx = e * T_TOKENS + r;
                        const float w = g_wt[idx];
                        const int tok = g_tok[idx];
                        const int slot = g_slot[idx];
                        float2 o = {v0 * w, v1 * w};
                        *(float2*)(g_contrib + ((size_t)tok * 2 + slot) * H_DIM + c) = o;
                    }
                } else {
                    const float sg = g_sgate[r];
                    const float2 c0 = *(const float2*)(g_contrib + ((size_t)r * 2 + 0) * H_DIM + c);
                    const float2 c1 = *(const float2*)(g_contrib + ((size_t)r * 2 + 1) * H_DIM + c);
                    float2 o = {sg * v0 + c0.x + c1.x, sg * v1 + c0.y + c1.y};
                    *(float2*)(outF + (size_t)r * H_DIM + c) = o;
                }
            }
        }
    }
}

// ---------------------------------------------------------------------------
extern "C" void kernel_launch(void* const* d_in, const int* in_sizes, int n_in,
                              void* d_out, int out_size)
{
    const float* hidden        = (const float*)d_in[0];
    const float* gate_w        = (const float*)d_in[1];
    const float* w_gate        = (const float*)d_in[2];
    const float* w_up          = (const float*)d_in[3];
    const float* w_down        = (const float*)d_in[4];
    const float* sw_gate       = (const float*)d_in[5];
    const float* sw_up         = (const float*)d_in[6];
    const float* sw_down       = (const float*)d_in[7];
    const float* shared_gate_w = (const float*)d_in[8];

    float* out        = (float*)d_out;
    float* out_logits = out + (size_t)T_TOKENS * H_DIM;

    bf16 *actHi, *actLo, *shHi, *shLo;
    cudaGetSymbolAddress((void**)&actHi, g_act_hi);
    cudaGetSymbolAddress((void**)&actLo, g_act_lo);
    cudaGetSymbolAddress((void**)&shHi, g_shact_hi);
    cudaGetSymbolAddress((void**)&shLo, g_shact_lo);

    zero_cnt_kernel<<<1, 32>>>();
    router_kernel<<<T_TOKENS, 256>>>(hidden, gate_w, shared_gate_w, out_logits);

    // expert gate+up fused -> act hi/lo
    gateup_mma_kernel<1><<<dim3(I_DIM / 64, T_TOKENS / 64, NE), 256>>>(
        hidden, w_gate, w_up, actHi, actLo, H_DIM, I_DIM);
    // expert down (scatter x routing weight)
    down_mma_kernel<1, 1><<<dim3(H_DIM / 64, T_TOKENS / 128, NE), 256>>>(
        actHi, actLo, w_down, nullptr, I_DIM, H_DIM);

    // shared gate+up fused -> shact hi/lo
    gateup_mma_kernel<0><<<dim3(SI_DIM / 64, T_TOKENS / 64, 1), 256>>>(
        hidden, sw_gate, sw_up, shHi, shLo, H_DIM, SI_DIM);
    // shared down + final combine
    down_mma_kernel<0, 2><<<dim3(H_DIM / 64, T_TOKENS / 128, 1), 256>>>(
        shHi, shLo, sw_down, out, SI_DIM, H_DIM);
}

// round 7
// speedup vs baseline: 2.3216x; 1.0004x over previous
#include <cuda_runtime.h>
#include <cuda_bf16.h>
#include <math.h>
#include <stdint.h>

#define T_TOKENS 1024
#define H_DIM    2048
#define I_DIM    1408
#define SI_DIM   5632
#define NE       8

typedef __nv_bfloat16 bf16;
typedef __nv_bfloat162 bf162;

// ---------------------------------------------------------------------------
// Scratch (__device__ globals; no cudaMalloc allowed)
// ---------------------------------------------------------------------------
__device__ int   g_cnt[NE];
__device__ int   g_tok [NE * T_TOKENS];
__device__ int   g_slot[NE * T_TOKENS];
__device__ float g_wt  [NE * T_TOKENS];
__device__ float g_sgate[T_TOKENS];

__device__ bf16  g_act_hi[(size_t)NE * T_TOKENS * I_DIM];
__device__ bf16  g_act_lo[(size_t)NE * T_TOKENS * I_DIM];
__device__ bf16  g_shact_hi[(size_t)T_TOKENS * SI_DIM];
__device__ bf16  g_shact_lo[(size_t)T_TOKENS * SI_DIM];
__device__ float g_contrib[(size_t)T_TOKENS * 2 * H_DIM];

// ---------------------------------------------------------------------------
__global__ void zero_cnt_kernel() {
    if (threadIdx.x < NE) g_cnt[threadIdx.x] = 0;
}

// Router (fp32)
__global__ __launch_bounds__(256) void router_kernel(
    const float* __restrict__ hidden,
    const float* __restrict__ gate_w,
    const float* __restrict__ shared_gate_w,
    float* __restrict__ out_logits)
{
    const int t = blockIdx.x;
    __shared__ float sh[H_DIM];
    __shared__ float slog[NE];
    __shared__ float sred[256];

    const float* hrow = hidden + (size_t)t * H_DIM;
    for (int i = threadIdx.x; i < H_DIM; i += 256) sh[i] = hrow[i];
    __syncthreads();

    const int warp = threadIdx.x >> 5;
    const int lane = threadIdx.x & 31;

    float sum = 0.f;
    for (int k = lane; k < H_DIM; k += 32) sum += sh[k] * gate_w[k * NE + warp];
    #pragma unroll
    for (int o = 16; o; o >>= 1) sum += __shfl_down_sync(0xffffffffu, sum, o);
    if (lane == 0) slog[warp] = sum;

    float s2 = 0.f;
    for (int k = threadIdx.x; k < H_DIM; k += 256) s2 += sh[k] * shared_gate_w[k];
    sred[threadIdx.x] = s2;
    __syncthreads();
    for (int st = 128; st; st >>= 1) {
        if (threadIdx.x < st) sred[threadIdx.x] += sred[threadIdx.x + st];
        __syncthreads();
    }

    if (threadIdx.x == 0) {
        float lg[NE];
        float mx = -1e30f;
        #pragma unroll
        for (int e = 0; e < NE; ++e) { lg[e] = slog[e]; mx = fmaxf(mx, lg[e]); }
        float p[NE]; float den = 0.f;
        #pragma unroll
        for (int e = 0; e < NE; ++e) { p[e] = expf(lg[e] - mx); den += p[e]; }
        float inv = 1.f / den;
        #pragma unroll
        for (int e = 0; e < NE; ++e) {
            p[e] *= inv;
            out_logits[(size_t)t * NE + e] = lg[e];
        }
        int i0 = 0;
        #pragma unroll
        for (int e = 1; e < NE; ++e) if (p[e] > p[i0]) i0 = e;
        int i1 = -1;
        #pragma unroll
        for (int e = 0; e < NE; ++e) {
            if (e == i0) continue;
            if (i1 < 0 || p[e] > p[i1]) i1 = e;
        }
        int pos0 = atomicAdd(&g_cnt[i0], 1);
        g_tok [i0 * T_TOKENS + pos0] = t;
        g_slot[i0 * T_TOKENS + pos0] = 0;
        g_wt  [i0 * T_TOKENS + pos0] = p[i0];
        int pos1 = atomicAdd(&g_cnt[i1], 1);
        g_tok [i1 * T_TOKENS + pos1] = t;
        g_slot[i1 * T_TOKENS + pos1] = 1;
        g_wt  [i1 * T_TOKENS + pos1] = p[i1];

        g_sgate[t] = 1.f / (1.f + expf(-sred[0]));
    }
}

// ---------------------------------------------------------------------------
// helpers
// ---------------------------------------------------------------------------
__device__ __forceinline__ uint32_t smem_u32(const void* p) {
    return (uint32_t)__cvta_generic_to_shared(p);
}
__device__ __forceinline__ void ldsm_x4(uint32_t& r0, uint32_t& r1, uint32_t& r2, uint32_t& r3, uint32_t a) {
    asm volatile("ldmatrix.sync.aligned.m8n8.x4.shared.b16 {%0,%1,%2,%3}, [%4];"
                 : "=r"(r0), "=r"(r1), "=r"(r2), "=r"(r3) : "r"(a));
}
__device__ __forceinline__ void ldsm_x4_t(uint32_t& r0, uint32_t& r1, uint32_t& r2, uint32_t& r3, uint32_t a) {
    asm volatile("ldmatrix.sync.aligned.m8n8.x4.trans.shared.b16 {%0,%1,%2,%3}, [%4];"
                 : "=r"(r0), "=r"(r1), "=r"(r2), "=r"(r3) : "r"(a));
}
__device__ __forceinline__ void mma16816(float* d, const uint32_t* a, uint32_t b0, uint32_t b1) {
    asm volatile("mma.sync.aligned.m16n8k16.row.col.f32.bf16.bf16.f32 "
                 "{%0,%1,%2,%3}, {%4,%5,%6,%7}, {%8,%9}, {%0,%1,%2,%3};"
                 : "+f"(d[0]), "+f"(d[1]), "+f"(d[2]), "+f"(d[3])
                 : "r"(a[0]), "r"(a[1]), "r"(a[2]), "r"(a[3]), "r"(b0), "r"(b1));
}
__device__ __forceinline__ void split4(const float4& v, uint2& hi, uint2& lo) {
    bf16 h0 = __float2bfloat16_rn(v.x), h1 = __float2bfloat16_rn(v.y);
    bf16 h2 = __float2bfloat16_rn(v.z), h3 = __float2bfloat16_rn(v.w);
    bf162 H0(h0, h1), H1(h2, h3);
    bf162 L0(__float2bfloat16_rn(v.x - __bfloat162float(h0)),
             __float2bfloat16_rn(v.y - __bfloat162float(h1)));
    bf162 L1(__float2bfloat16_rn(v.z - __bfloat162float(h2)),
             __float2bfloat16_rn(v.w - __bfloat162float(h3)));
    hi.x = *reinterpret_cast<uint32_t*>(&H0); hi.y = *reinterpret_cast<uint32_t*>(&H1);
    lo.x = *reinterpret_cast<uint32_t*>(&L0); lo.y = *reinterpret_cast<uint32_t*>(&L1);
}
__device__ __forceinline__ void split2(float a, float b, uint32_t& hi, uint32_t& lo) {
    bf16 h0 = __float2bfloat16_rn(a), h1 = __float2bfloat16_rn(b);
    bf162 H(h0, h1);
    bf162 L(__float2bfloat16_rn(a - __bfloat162float(h0)),
            __float2bfloat16_rn(b - __bfloat162float(h1)));
    hi = *reinterpret_cast<uint32_t*>(&H);
    lo = *reinterpret_cast<uint32_t*>(&L);
}

// ---------------------------------------------------------------------------
// Fused dual-B gate+up GEMM (warp-split across matrices).
// Tile 64(M) x 64(N per matrix). 256 threads = 8 warps: 2m x 2n x 2(matrix).
// Each warp computes a 32x32 tile of EITHER gate or up; epilogue exchanges
// up-accumulators through smem, g-warps apply silu(g)*u -> bf16 hi/lo.
// ---------------------------------------------------------------------------
template<int GATHER>
__global__ __launch_bounds__(256, 2) void gateup_mma_kernel(
    const float* __restrict__ A,
    const float* __restrict__ Bg_, const float* __restrict__ Bu_,
    bf16* __restrict__ outHi, bf16* __restrict__ outLo,
    int K, int Ntot)
{
    const int e  = blockIdx.z;
    const int m0 = blockIdx.y * 64;
    const int n0 = blockIdx.x * 64;
    const int cnt = GATHER ? g_cnt[e] : T_TOKENS;
    if (m0 >= cnt) return;

    __shared__ bf16 AsHi[64][40];
    __shared__ bf16 AsLo[64][40];
    __shared__ bf16 BgHi[32][72];
    __shared__ bf16 BgLo[32][72];
    __shared__ bf16 BuHi[32][72];
    __shared__ bf16 BuLo[32][72];
    __shared__ float exch[64][72];
    __shared__ int  s_tok[64];

    const int tid  = threadIdx.x;
    const int lane = tid & 31;
    const int warp = tid >> 5;
    const int wm   = warp & 1;
    const int wn   = (warp >> 1) & 1;
    const int wmat = warp >> 2;          // 0=gate, 1=up

    if (GATHER && tid < 64) {
        int gm = m0 + tid;
        s_tok[tid] = (gm < cnt) ? g_tok[e * T_TOKENS + gm] : 0;
    }
    __syncthreads();

    // A: 64 rows x 32 k fp32; 4 threads/row, 8 k each
    const int ar = tid >> 2;
    const int ac = (tid & 3) * 8;
    size_t arow_off;
    if (GATHER) arow_off = (size_t)s_tok[ar] * K;
    else        arow_off = (size_t)(m0 + ar) * K;

    // B: 32 rows x 64 n per matrix; 8 threads/row, 8 n each
    const int br = tid >> 3;
    const int bc = (tid & 7) * 8;
    const float* BgP = Bg_ + (GATHER ? (size_t)e * K * Ntot : 0) + n0 + bc;
    const float* BuP = Bu_ + (GATHER ? (size_t)e * K * Ntot : 0) + n0 + bc;

    float4 pa[2], pbg[2], pbu[2];
    auto load_regs = [&](int k0) {
        #pragma unroll
        for (int c = 0; c < 2; ++c) pa[c] = *(const float4*)(A + arow_off + k0 + ac + c * 4);
        #pragma unroll
        for (int c = 0; c < 2; ++c) {
            pbg[c] = *(const float4*)(BgP + (size_t)(k0 + br) * Ntot + c * 4);
            pbu[c] = *(const float4*)(BuP + (size_t)(k0 + br) * Ntot + c * 4);
        }
    };
    auto sts_regs = [&]() {
        #pragma unroll
        for (int c = 0; c < 2; ++c) {
            uint2 h, l; split4(pa[c], h, l);
            *(uint2*)&AsHi[ar][ac + c * 4] = h;
            *(uint2*)&AsLo[ar][ac + c * 4] = l;
        }
        #pragma unroll
        for (int c = 0; c < 2; ++c) {
            uint2 h, l;
            split4(pbg[c], h, l);
            *(uint2*)&BgHi[br][bc + c * 4] = h; *(uint2*)&BgLo[br][bc + c * 4] = l;
            split4(pbu[c], h, l);
            *(uint2*)&BuHi[br][bc + c * 4] = h; *(uint2*)&BuLo[br][bc + c * 4] = l;
        }
    };

    float acc[2][4][4];
    #pragma unroll
    for (int i = 0; i < 2; ++i)
        #pragma unroll
        for (int j = 0; j < 4; ++j)
            #pragma unroll
            for (int v = 0; v < 4; ++v) acc[i][j][v] = 0.f;

    const int grp = lane >> 3;
    const int gl  = lane & 7;
    const int a_row_off = (grp & 1) * 8 + gl;
    const int a_col_off = (grp >> 1) * 8;
    const int b_row_off = (grp & 1) * 8 + gl;
    const int b_col_off = (grp >> 1) * 8;

    bf16 (*BH)[72] = wmat ? BuHi : BgHi;
    bf16 (*BL)[72] = wmat ? BuLo : BgLo;

    load_regs(0);
    for (int k0 = 0; k0 < K; k0 += 32) {
        sts_regs();
        __syncthreads();
        if (k0 + 32 < K) load_regs(k0 + 32);

        #pragma unroll
        for (int ks = 0; ks < 32; ks += 16) {
            uint32_t ah[2][4], al[2][4];
            #pragma unroll
            for (int mi = 0; mi < 2; ++mi) {
                uint32_t addr = smem_u32(&AsHi[wm * 32 + mi * 16 + a_row_off][ks + a_col_off]);
                ldsm_x4(ah[mi][0], ah[mi][1], ah[mi][2], ah[mi][3], addr);
                addr = smem_u32(&AsLo[wm * 32 + mi * 16 + a_row_off][ks + a_col_off]);
                ldsm_x4(al[mi][0], al[mi][1], al[mi][2], al[mi][3], addr);
            }
            uint32_t bh[2][4], bl[2][4];
            #pragma unroll
            for (int g = 0; g < 2; ++g) {
                uint32_t addr = smem_u32(&BH[ks + b_row_off][wn * 32 + g * 16 + b_col_off]);
                ldsm_x4_t(bh[g][0], bh[g][1], bh[g][2], bh[g][3], addr);
                addr = smem_u32(&BL[ks + b_row_off][wn * 32 + g * 16 + b_col_off]);
                ldsm_x4_t(bl[g][0], bl[g][1], bl[g][2], bl[g][3], addr);
            }
            #pragma unroll
            for (int mi = 0; mi < 2; ++mi) {
                #pragma unroll
                for (int nj = 0; nj < 4; ++nj) {
                    const int g = nj >> 1, p = (nj & 1) * 2;
                    mma16816(acc[mi][nj], ah[mi], bh[g][p], bh[g][p + 1]);
                    mma16816(acc[mi][nj], ah[mi], bl[g][p], bl[g][p + 1]);
                    mma16816(acc[mi][nj], al[mi], bh[g][p], bh[g][p + 1]);
                }
            }
        }
        __syncthreads();
    }

    // epilogue: u-warps publish, g-warps combine
    const int rl_base = wm * 32 + (lane >> 2);
    const int cl_base = wn * 32 + (lane & 3) * 2;

    if (wmat == 1) {
        #pragma unroll
        for (int mi = 0; mi < 2; ++mi)
            #pragma unroll
            for (int half = 0; half < 2; ++half) {
                const int rl = rl_base + mi * 16 + half * 8;
                #pragma unroll
                for (int nj = 0; nj < 4; ++nj) {
                    const int cl = cl_base + nj * 8;
                    exch[rl][cl]     = acc[mi][nj][half * 2];
                    exch[rl][cl + 1] = acc[mi][nj][half * 2 + 1];
                }
            }
    }
    __syncthreads();
    if (wmat == 0) {
        #pragma unroll
        for (int mi = 0; mi < 2; ++mi)
            #pragma unroll
            for (int half = 0; half < 2; ++half) {
                const int rl = rl_base + mi * 16 + half * 8;
                const int r = m0 + rl;
                if (GATHER && r >= cnt) continue;
                const size_t row = (size_t)(GATHER ? e * T_TOKENS : 0) + r;
                #pragma unroll
                for (int nj = 0; nj < 4; ++nj) {
                    const int cl = cl_base + nj * 8;
                    float g0 = acc[mi][nj][half * 2];
                    float g1 = acc[mi][nj][half * 2 + 1];
                    float u0 = exch[rl][cl];
                    float u1 = exch[rl][cl + 1];
                    float a0 = (g0 / (1.f + expf(-g0))) * u0;
                    float a1 = (g1 / (1.f + expf(-g1))) * u1;
                    uint32_t hi, lo; split2(a0, a1, hi, lo);
                    *(uint32_t*)(outHi + row * Ntot + n0 + cl) = hi;
                    *(uint32_t*)(outLo + row * Ntot + n0 + cl) = lo;
                }
            }
    }
}

// ---------------------------------------------------------------------------
// Down GEMM: A bf16 hi/lo, B fp32 (split in-kernel).
// Tile 128(M) x 64(N), 256 threads = 8 warps (4m x 2n), warp tile 32x32.
// EPI=1: expert scatter (x routing weight into g_contrib)
// EPI=2: shared combine (sigmoid gate + contrib -> out)
// ---------------------------------------------------------------------------
template<int AEXP, int EPI>
__global__ __launch_bounds__(256, 2) void down_mma_kernel(
    const bf16* __restrict__ Ahi, const bf16* __restrict__ Alo,
    const float* __restrict__ B_,
    float* __restrict__ outF, int K, int N)
{
    const int e  = blockIdx.z;
    const int m0 = blockIdx.y * 128;
    const int n0 = blockIdx.x * 64;
    const int cnt = AEXP ? g_cnt[e] : T_TOKENS;
    if (m0 >= cnt) return;

    __shared__ bf16 AsHi[128][40];
    __shared__ bf16 AsLo[128][40];
    __shared__ bf16 BsHi[32][72];
    __shared__ bf16 BsLo[32][72];

    const int tid  = threadIdx.x;
    const int lane = tid & 31;
    const int warp = tid >> 5;
    const int wm = warp & 3;
    const int wn = warp >> 2;

    // A: 128 rows x 32 k halves; 2 threads/row, 16 halves each (uint4 x2)
    const int ar = tid >> 1;
    const int ac = (tid & 1) * 16;
    const size_t abase = (size_t)m0 + (AEXP ? (size_t)e * T_TOKENS : 0);
    const size_t aoff = (abase + ar) * K;

    // B: fp32 32 x 64; 8 threads/row, 8 n each
    const int br = tid >> 3;
    const int bc = (tid & 7) * 8;
    const float* BP = B_ + (AEXP ? (size_t)e * K * N : 0) + n0 + bc;

    uint4  pah[2], pal[2];
    float4 pb[2];
    auto load_regs = [&](int k0) {
        pah[0] = *(const uint4*)(Ahi + aoff + k0 + ac);
        pah[1] = *(const uint4*)(Ahi + aoff + k0 + ac + 8);
        pal[0] = *(const uint4*)(Alo + aoff + k0 + ac);
        pal[1] = *(const uint4*)(Alo + aoff + k0 + ac + 8);
        pb[0] = *(const float4*)(BP + (size_t)(k0 + br) * N);
        pb[1] = *(const float4*)(BP + (size_t)(k0 + br) * N + 4);
    };
    auto sts_regs = [&]() {
        *(uint4*)&AsHi[ar][ac]     = pah[0];
        *(uint4*)&AsHi[ar][ac + 8] = pah[1];
        *(uint4*)&AsLo[ar][ac]     = pal[0];
        *(uint4*)&AsLo[ar][ac + 8] = pal[1];
        uint2 h, l;
        split4(pb[0], h, l);
        *(uint2*)&BsHi[br][bc] = h; *(uint2*)&BsLo[br][bc] = l;
        split4(pb[1], h, l);
        *(uint2*)&BsHi[br][bc + 4] = h; *(uint2*)&BsLo[br][bc + 4] = l;
    };

    float acc[2][4][4];
    #pragma unroll
    for (int i = 0; i < 2; ++i)
        #pragma unroll
        for (int j = 0; j < 4; ++j)
            #pragma unroll
            for (int v = 0; v < 4; ++v) acc[i][j][v] = 0.f;

    const int grp = lane >> 3;
    const int gl  = lane & 7;
    const int a_row_off = (grp & 1) * 8 + gl;
    const int a_col_off = (grp >> 1) * 8;
    const int b_row_off = (grp & 1) * 8 + gl;
    const int b_col_off = (grp >> 1) * 8;

    load_regs(0);
    for (int k0 = 0; k0 < K; k0 += 32) {
        sts_regs();
        __syncthreads();
        if (k0 + 32 < K) load_regs(k0 + 32);

        #pragma unroll
        for (int ks = 0; ks < 32; ks += 16) {
            uint32_t ah[2][4], al[2][4];
            #pragma unroll
            for (int mi = 0; mi < 2; ++mi) {
                uint32_t addr = smem_u32(&AsHi[wm * 32 + mi * 16 + a_row_off][ks + a_col_off]);
                ldsm_x4(ah[mi][0], ah[mi][1], ah[mi][2], ah[mi][3], addr);
                addr = smem_u32(&AsLo[wm * 32 + mi * 16 + a_row_off][ks + a_col_off]);
                ldsm_x4(al[mi][0], al[mi][1], al[mi][2], al[mi][3], addr);
            }
            uint32_t bh[2][4], bl[2][4];
            #pragma unroll
            for (int g = 0; g < 2; ++g) {
                uint32_t addr = smem_u32(&BsHi[ks + b_row_off][wn * 32 + g * 16 + b_col_off]);
                ldsm_x4_t(bh[g][0], bh[g][1], bh[g][2], bh[g][3], addr);
                addr = smem_u32(&BsLo[ks + b_row_off][wn * 32 + g * 16 + b_col_off]);
                ldsm_x4_t(bl[g][0], bl[g][1], bl[g][2], bl[g][3], addr);
            }
            #pragma unroll
            for (int mi = 0; mi < 2; ++mi) {
                #pragma unroll
                for (int nj = 0; nj < 4; ++nj) {
                    const int g = nj >> 1, p = (nj & 1) * 2;
                    mma16816(acc[mi][nj], ah[mi], bh[g][p], bh[g][p + 1]);
                    mma16816(acc[mi][nj], ah[mi], bl[g][p], bl[g][p + 1]);
                    mma16816(acc[mi][nj], al[mi], bh[g][p], bh[g][p + 1]);
                }
            }
        }
        __syncthreads();
    }

    const int rbase = m0 + wm * 32 + (lane >> 2);
    const int cbase = n0 + wn * 32 + (lane & 3) * 2;
    #pragma unroll
    for (int mi = 0; mi < 2; ++mi) {
        #pragma unroll
        for (int half = 0; half < 2; ++half) {
            const int r = rbase + mi * 16 + half * 8;
            #pragma unroll
            for (int nj = 0; nj < 4; ++nj) {
                const int c = cbase + nj * 8;
                float v0 = acc[mi][nj][half * 2];
                float v1 = acc[mi][nj][half * 2 + 1];
                if (EPI == 1) {
                    if (r < cnt) {
                        const int idx = e * T_TOKENS + r;
                        const float w = g_wt[idx];
                        const int tok = g_tok[idx];
                        const int slot = g_slot[idx];
                        float2 o = {v0 * w, v1 * w};
                        *(float2*)(g_contrib + ((size_t)tok * 2 + slot) * H_DIM + c) = o;
                    }
                } else {
                    const float sg = g_sgate[r];
                    const float2 c0 = *(const float2*)(g_contrib + ((size_t)r * 2 + 0) * H_DIM + c);
                    const float2 c1 = *(const float2*)(g_contrib + ((size_t)r * 2 + 1) * H_DIM + c);
                    float2 o = {sg * v0 + c0.x + c1.x, sg * v1 + c0.y + c1.y};
                    *(float2*)(outF + (size_t)r * H_DIM + c) = o;
                }
            }
        }
    }
}

// ---------------------------------------------------------------------------
extern "C" void kernel_launch(void* const* d_in, const int* in_sizes, int n_in,
                              void* d_out, int out_size)
{
    const float* hidden        = (const float*)d_in[0];
    const float* gate_w        = (const float*)d_in[1];
    const float* w_gate        = (const float*)d_in[2];
    const float* w_up          = (const float*)d_in[3];
    const float* w_down        = (const float*)d_in[4];
    const float* sw_gate       = (const float*)d_in[5];
    const float* sw_up         = (const float*)d_in[6];
    const float* sw_down       = (const float*)d_in[7];
    const float* shared_gate_w = (const float*)d_in[8];

    float* out        = (float*)d_out;
    float* out_logits = out + (size_t)T_TOKENS * H_DIM;

    bf16 *actHi, *actLo, *shHi, *shLo;
    cudaGetSymbolAddress((void**)&actHi, g_act_hi);
    cudaGetSymbolAddress((void**)&actLo, g_act_lo);
    cudaGetSymbolAddress((void**)&shHi, g_shact_hi);
    cudaGetSymbolAddress((void**)&shLo, g_shact_lo);

    zero_cnt_kernel<<<1, 32>>>();
    router_kernel<<<T_TOKENS, 256>>>(hidden, gate_w, shared_gate_w, out_logits);

    // expert gate+up fused -> act hi/lo
    gateup_mma_kernel<1><<<dim3(I_DIM / 64, T_TOKENS / 64, NE), 256>>>(
        hidden, w_gate, w_up, actHi, actLo, H_DIM, I_DIM);
    // expert down (scatter x routing weight)
    down_mma_kernel<1, 1><<<dim3(H_DIM / 64, T_TOKENS / 128, NE), 256>>>(
        actHi, actLo, w_down, nullptr, I_DIM, H_DIM);

    // shared gate+up fused -> shact hi/lo
    gateup_mma_kernel<0><<<dim3(SI_DIM / 64, T_TOKENS / 64, 1), 256>>>(
        hidden, sw_gate, sw_up, shHi, shLo, H_DIM, SI_DIM);
    // shared down + final combine
    down_mma_kernel<0, 2><<<dim3(H_DIM / 64, T_TOKENS / 128, 1), 256>>>(
        shHi, shLo, sw_down, out, SI_DIM, H_DIM);
}